// round 3
// baseline (speedup 1.0000x reference)
#include <cuda_runtime.h>
#include <cuda_bf16.h>
#include <math.h>
#include <stdint.h>

#define B_  512
#define T_  512
#define L_  64
#define H_  512
#define G3_ 1536
#define KC_ 1536          // concatenated K (hi | hi | lo)
#define XW_ (T_ + L_ - 1) // 575

// ------------------------- device scratch (no allocs) -----------------------
__device__ float g_GI1[(size_t)L_ * B_ * G3_];     // [t][b][3H] input proj (+b_ih1)
__device__ float g_H1f[2][(size_t)B_ * H_];        // fp32 h1 ping-pong
__device__ float g_H2[(size_t)L_ * B_ * H_];       // fp32 h2 history

// concatenated bf16 operands: A' = [hi | hi | lo], B' = [hi | lo | hi]
__device__ __nv_bfloat16 g_W0c[(size_t)G3_ * KC_];   // W_ih1 (K=T=512)
__device__ __nv_bfloat16 g_W1c[(size_t)G3_ * KC_];   // W_hh1
__device__ __nv_bfloat16 g_W2c[(size_t)G3_ * KC_];   // W_ih2
__device__ __nv_bfloat16 g_W3c[(size_t)G3_ * KC_];   // W_hh2
__device__ __nv_bfloat16 g_H1c[2][(size_t)B_ * KC_];
__device__ __nv_bfloat16 g_H2c[2][(size_t)B_ * KC_];
__device__ __nv_bfloat16 g_Xc[(size_t)L_ * B_ * KC_]; // windowed x, per t

__device__ __forceinline__ float sigm(float v) { return 1.f / (1.f + __expf(-v)); }

__device__ __forceinline__ uint32_t smem_u32(const void* p) {
    uint32_t a;
    asm("{ .reg .u64 t; cvta.to.shared.u64 t, %1; cvt.u32.u64 %0, t; }" : "=r"(a) : "l"(p));
    return a;
}
__device__ __forceinline__ void ldsm4(uint32_t* r, uint32_t addr) {
    asm volatile("ldmatrix.sync.aligned.m8n8.x4.shared.b16 {%0,%1,%2,%3}, [%4];"
                 : "=r"(r[0]), "=r"(r[1]), "=r"(r[2]), "=r"(r[3]) : "r"(addr));
}
__device__ __forceinline__ void mma16816(float* c, const uint32_t* a, uint32_t b0, uint32_t b1) {
    asm volatile("mma.sync.aligned.m16n8k16.row.col.f32.bf16.bf16.f32 "
                 "{%0,%1,%2,%3}, {%4,%5,%6,%7}, {%8,%9}, {%0,%1,%2,%3};"
                 : "+f"(c[0]), "+f"(c[1]), "+f"(c[2]), "+f"(c[3])
                 : "r"(a[0]), "r"(a[1]), "r"(a[2]), "r"(a[3]), "r"(b0), "r"(b1));
}
__device__ __forceinline__ void split2(float a, __nv_bfloat16& h, __nv_bfloat16& l) {
    h = __float2bfloat16_rn(a);
    l = __float2bfloat16_rn(a - __bfloat162float(h));
}

// stage `rows` x 32 bf16 from row-major src (stride KC_) into padded smem (80B rows)
__device__ __forceinline__ void stage_rows(char* dst, const __nv_bfloat16* src,
                                           int rows, int tid) {
    for (int i = tid; i < rows * 4; i += 128) {
        int r = i >> 2, q = i & 3;
        *(uint4*)(dst + r * 80 + q * 16) =
            *(const uint4*)(src + (size_t)r * KC_ + q * 8);
    }
}

// ---------------------------------------------------------------------------
// Prep kernels
// ---------------------------------------------------------------------------
__global__ __launch_bounds__(256) void k_prep_w(const float* __restrict__ W0,
                                                const float* __restrict__ W1,
                                                const float* __restrict__ W2,
                                                const float* __restrict__ W3) {
    size_t i = (size_t)blockIdx.x * 256 + threadIdx.x;
    if (i >= (size_t)G3_ * H_) return;
    size_t j = i / H_, k = i % H_;
    size_t o = j * KC_ + k;
    __nv_bfloat16 h, l;
    split2(W0[i], h, l); g_W0c[o] = h; g_W0c[o + H_] = l; g_W0c[o + 2 * H_] = h;
    split2(W1[i], h, l); g_W1c[o] = h; g_W1c[o + H_] = l; g_W1c[o + 2 * H_] = h;
    split2(W2[i], h, l); g_W2c[o] = h; g_W2c[o + H_] = l; g_W2c[o + 2 * H_] = h;
    split2(W3[i], h, l); g_W3c[o] = h; g_W3c[o + H_] = l; g_W3c[o + 2 * H_] = h;
}

__global__ __launch_bounds__(256) void k_prep_h(const float* __restrict__ h1i,
                                                const float* __restrict__ h2i) {
    size_t i = (size_t)blockIdx.x * 256 + threadIdx.x;
    if (i >= (size_t)B_ * H_) return;
    size_t b = i / H_, k = i % H_;
    size_t o = b * KC_ + k;
    __nv_bfloat16 h, l;
    float a = h1i[i];
    split2(a, h, l); g_H1c[1][o] = h; g_H1c[1][o + H_] = h; g_H1c[1][o + 2 * H_] = l;
    g_H1f[1][i] = a;
    split2(h2i[i], h, l); g_H2c[1][o] = h; g_H2c[1][o + H_] = h; g_H2c[1][o + 2 * H_] = l;
}

__global__ __launch_bounds__(256) void k_prep_x(const float* __restrict__ x) {
    size_t i = (size_t)blockIdx.x * 256 + threadIdx.x;
    if (i >= (size_t)L_ * B_ * H_) return;
    int k = (int)(i % H_);
    int b = (int)((i / H_) % B_);
    int t = (int)(i / ((size_t)B_ * H_));
    float a = x[(size_t)b * XW_ + t + k];
    __nv_bfloat16 h, l;
    split2(a, h, l);
    size_t o = ((size_t)t * B_ + b) * KC_ + k;
    g_Xc[o] = h; g_Xc[o + H_] = h; g_Xc[o + 2 * H_] = l;
}

// ---------------------------------------------------------------------------
// k_gi1_tc: GI1[t][b][3H] = Xc[t] @ W0c^T + b_ih1.
// CTA: M=64 (batch), Ngate=64 x 3 gates. grid (8 j, 8 m, 64 t), 128 threads.
// smem/buf: A 64x80=5120, B 3x(64x80)=15360 -> 20480; double buffer 40960.
// ---------------------------------------------------------------------------
__global__ __launch_bounds__(128, 1) void k_gi1_tc(const float* __restrict__ bias) {
    extern __shared__ char sm[];
    const int tid = threadIdx.x;
    const int j0 = blockIdx.x * 64;
    const int m0 = blockIdx.y * 64;
    const int t  = blockIdx.z;
    const __nv_bfloat16* A = g_Xc + ((size_t)t * B_ + m0) * KC_;
    const uint32_t smb = smem_u32(sm);

    const int wid = tid >> 5, lane = tid & 31;
    const int wm = (wid >> 1) * 32, wn = (wid & 1) * 32;
    const int a_row = lane & 15, a_col = (lane >> 4) * 8;
    const int b_row = (lane & 7) + ((lane >> 4) << 3), b_col = ((lane >> 3) & 1) * 8;

    float acc[3][2][4][4];
#pragma unroll
    for (int g = 0; g < 3; g++)
#pragma unroll
        for (int mt = 0; mt < 2; mt++)
#pragma unroll
            for (int nt = 0; nt < 4; nt++)
#pragma unroll
                for (int q = 0; q < 4; q++) acc[g][mt][nt][q] = 0.f;

    auto stage = [&](int c, int buf) {
        const int k0 = c * 32;
        char* d = sm + buf * 20480;
        stage_rows(d, A + k0, 64, tid);
#pragma unroll
        for (int g = 0; g < 3; g++)
            stage_rows(d + 5120 + g * 5120, g_W0c + (size_t)(g * 512 + j0) * KC_ + k0, 64, tid);
    };

    stage(0, 0);
    __syncthreads();
    for (int c = 0; c < 48; c++) {
        const int cur = c & 1;
        if (c + 1 < 48) stage(c + 1, cur ^ 1);
        const uint32_t Ab = smb + cur * 20480;
#pragma unroll
        for (int h = 0; h < 2; h++) {
            const int c0 = h * 16;
            uint32_t a[2][4];
#pragma unroll
            for (int mt = 0; mt < 2; mt++)
                ldsm4(a[mt], Ab + ((wm + mt * 16 + a_row) * 40 + c0 + a_col) * 2);
#pragma unroll
            for (int g = 0; g < 3; g++) {
                uint32_t b[8];
#pragma unroll
                for (int nn = 0; nn < 2; nn++)
                    ldsm4(b + nn * 4, Ab + 5120 + g * 5120 +
                          ((wn + nn * 16 + b_row) * 40 + c0 + b_col) * 2);
#pragma unroll
                for (int mt = 0; mt < 2; mt++)
#pragma unroll
                    for (int nt = 0; nt < 4; nt++)
                        mma16816(acc[g][mt][nt], a[mt], b[nt * 2], b[nt * 2 + 1]);
            }
        }
        __syncthreads();
    }

    const int row = lane >> 2, colp = (lane & 3) * 2;
    float* gi = g_GI1 + ((size_t)t * B_ + m0) * G3_;
#pragma unroll
    for (int g = 0; g < 3; g++)
#pragma unroll
        for (int mt = 0; mt < 2; mt++)
#pragma unroll
            for (int nt = 0; nt < 4; nt++) {
                int jg = j0 + wn + nt * 8 + colp;
                float2 bv = *(const float2*)(bias + g * 512 + jg);
#pragma unroll
                for (int hh = 0; hh < 2; hh++) {
                    int m = wm + mt * 16 + row + hh * 8;
                    float2 o;
                    o.x = acc[g][mt][nt][hh * 2 + 0] + bv.x;
                    o.y = acc[g][mt][nt][hh * 2 + 1] + bv.y;
                    *(float2*)(gi + (size_t)m * G3_ + g * 512 + jg) = o;
                }
            }
}

// ---------------------------------------------------------------------------
// k_step1_tc: h1' = GRU1(gi1[t], h1). CTA: M=64, Ngate=32 x 3. grid (16, 8).
// smem/buf: A 5120 + B 3x2560 = 12800; double buffer 25600.
// ---------------------------------------------------------------------------
__global__ __launch_bounds__(128, 1) void k_step1_tc(int t, const float* __restrict__ bhh) {
    extern __shared__ char sm[];
    const int tid = threadIdx.x;
    const int j0 = blockIdx.x * 32;
    const int m0 = blockIdx.y * 64;
    const int oldp = (t + 1) & 1, newp = t & 1;
    const __nv_bfloat16* A = g_H1c[oldp] + (size_t)m0 * KC_;
    const uint32_t smb = smem_u32(sm);

    const int wid = tid >> 5, lane = tid & 31;
    const int wm = (wid >> 1) * 32, wn = (wid & 1) * 16;
    const int a_row = lane & 15, a_col = (lane >> 4) * 8;
    const int b_row = (lane & 7) + ((lane >> 4) << 3), b_col = ((lane >> 3) & 1) * 8;

    float acc[3][2][2][4];
#pragma unroll
    for (int g = 0; g < 3; g++)
#pragma unroll
        for (int mt = 0; mt < 2; mt++)
#pragma unroll
            for (int nt = 0; nt < 2; nt++)
#pragma unroll
                for (int q = 0; q < 4; q++) acc[g][mt][nt][q] = 0.f;

    auto stage = [&](int c, int buf) {
        const int k0 = c * 32;
        char* d = sm + buf * 12800;
        stage_rows(d, A + k0, 64, tid);
#pragma unroll
        for (int g = 0; g < 3; g++)
            stage_rows(d + 5120 + g * 2560, g_W1c + (size_t)(g * 512 + j0) * KC_ + k0, 32, tid);
    };

    stage(0, 0);
    __syncthreads();
    for (int c = 0; c < 48; c++) {
        const int cur = c & 1;
        if (c + 1 < 48) stage(c + 1, cur ^ 1);
        const uint32_t Ab = smb + cur * 12800;
#pragma unroll
        for (int h = 0; h < 2; h++) {
            const int c0 = h * 16;
            uint32_t a[2][4];
#pragma unroll
            for (int mt = 0; mt < 2; mt++)
                ldsm4(a[mt], Ab + ((wm + mt * 16 + a_row) * 40 + c0 + a_col) * 2);
#pragma unroll
            for (int g = 0; g < 3; g++) {
                uint32_t b[4];
                ldsm4(b, Ab + 5120 + g * 2560 + ((wn + b_row) * 40 + c0 + b_col) * 2);
#pragma unroll
                for (int mt = 0; mt < 2; mt++)
#pragma unroll
                    for (int nt = 0; nt < 2; nt++)
                        mma16816(acc[g][mt][nt], a[mt], b[nt * 2], b[nt * 2 + 1]);
            }
        }
        __syncthreads();
    }

    const int row = lane >> 2, colp = (lane & 3) * 2;
    const float* hfO = g_H1f[oldp];
    float* hfN = g_H1f[newp];
    __nv_bfloat16* hc = g_H1c[newp];
#pragma unroll
    for (int mt = 0; mt < 2; mt++)
#pragma unroll
        for (int nt = 0; nt < 2; nt++) {
            int jg = j0 + wn + nt * 8 + colp;
            float2 br = *(const float2*)(bhh + jg);
            float2 bz = *(const float2*)(bhh + 512 + jg);
            float2 bn = *(const float2*)(bhh + 1024 + jg);
#pragma unroll
            for (int hh = 0; hh < 2; hh++) {
                int m = m0 + wm + mt * 16 + row + hh * 8;
                const float* gi = g_GI1 + ((size_t)t * B_ + m) * G3_;
                float2 gr = *(const float2*)(gi + jg);
                float2 gz = *(const float2*)(gi + 512 + jg);
                float2 gn = *(const float2*)(gi + 1024 + jg);
                float vr0 = acc[0][mt][nt][hh * 2], vr1 = acc[0][mt][nt][hh * 2 + 1];
                float vz0 = acc[1][mt][nt][hh * 2], vz1 = acc[1][mt][nt][hh * 2 + 1];
                float vn0 = acc[2][mt][nt][hh * 2], vn1 = acc[2][mt][nt][hh * 2 + 1];
                float r0 = sigm(gr.x + vr0 + br.x), r1 = sigm(gr.y + vr1 + br.y);
                float z0 = sigm(gz.x + vz0 + bz.x), z1 = sigm(gz.y + vz1 + bz.y);
                float n0 = tanhf(gn.x + r0 * (vn0 + bn.x));
                float n1 = tanhf(gn.y + r1 * (vn1 + bn.y));
                float2 ho = *(const float2*)(hfO + (size_t)m * H_ + jg);
                float h0 = (1.f - z0) * n0 + z0 * ho.x;
                float h1 = (1.f - z1) * n1 + z1 * ho.y;
                *(float2*)(hfN + (size_t)m * H_ + jg) = make_float2(h0, h1);
                __nv_bfloat16 a0, l0, a1, l1;
                split2(h0, a0, l0); split2(h1, a1, l1);
                __nv_bfloat162 hv; hv.x = a0; hv.y = a1;
                __nv_bfloat162 lv; lv.x = l0; lv.y = l1;
                *(__nv_bfloat162*)(hc + (size_t)m * KC_ + jg) = hv;
                *(__nv_bfloat162*)(hc + (size_t)m * KC_ + 512 + jg) = hv;
                *(__nv_bfloat162*)(hc + (size_t)m * KC_ + 1024 + jg) = lv;
            }
        }
}

// ---------------------------------------------------------------------------
// k_step2_tc: h2' = GRU2(h1', h2). Two A operands; r/z accumulate both matmuls,
// i_n / h_n separate. CTA: M=64, Ngate=32 x 3. grid (16, 8).
// smem/buf: 2x5120 + 6x2560 = 25600; double buffer 51200.
// ---------------------------------------------------------------------------
__global__ __launch_bounds__(128, 1) void k_step2_tc(int t, const float* __restrict__ h2i,
                                                     const float* __restrict__ bih,
                                                     const float* __restrict__ bhh) {
    extern __shared__ char sm[];
    const int tid = threadIdx.x;
    const int j0 = blockIdx.x * 32;
    const int m0 = blockIdx.y * 64;
    const int oldp = (t + 1) & 1, newp = t & 1;
    const __nv_bfloat16* A1 = g_H1c[newp] + (size_t)m0 * KC_;
    const __nv_bfloat16* A2 = g_H2c[oldp] + (size_t)m0 * KC_;
    const uint32_t smb = smem_u32(sm);

    const int wid = tid >> 5, lane = tid & 31;
    const int wm = (wid >> 1) * 32, wn = (wid & 1) * 16;
    const int a_row = lane & 15, a_col = (lane >> 4) * 8;
    const int b_row = (lane & 7) + ((lane >> 4) << 3), b_col = ((lane >> 3) & 1) * 8;

    float aR[2][2][4], aZ[2][2][4], aI[2][2][4], aH[2][2][4];
#pragma unroll
    for (int mt = 0; mt < 2; mt++)
#pragma unroll
        for (int nt = 0; nt < 2; nt++)
#pragma unroll
            for (int q = 0; q < 4; q++) {
                aR[mt][nt][q] = 0.f; aZ[mt][nt][q] = 0.f;
                aI[mt][nt][q] = 0.f; aH[mt][nt][q] = 0.f;
            }

    auto stage = [&](int c, int buf) {
        const int k0 = c * 32;
        char* d = sm + buf * 25600;
        stage_rows(d, A1 + k0, 64, tid);
        stage_rows(d + 5120, A2 + k0, 64, tid);
#pragma unroll
        for (int g = 0; g < 3; g++) {
            stage_rows(d + 10240 + g * 2560,
                       g_W2c + (size_t)(g * 512 + j0) * KC_ + k0, 32, tid);
            stage_rows(d + 10240 + (3 + g) * 2560,
                       g_W3c + (size_t)(g * 512 + j0) * KC_ + k0, 32, tid);
        }
    };

    stage(0, 0);
    __syncthreads();
    for (int c = 0; c < 48; c++) {
        const int cur = c & 1;
        if (c + 1 < 48) stage(c + 1, cur ^ 1);
        const uint32_t Ab = smb + cur * 25600;
#pragma unroll
        for (int h = 0; h < 2; h++) {
            const int c0 = h * 16;
            uint32_t a1[2][4], a2[2][4];
#pragma unroll
            for (int mt = 0; mt < 2; mt++) {
                ldsm4(a1[mt], Ab + ((wm + mt * 16 + a_row) * 40 + c0 + a_col) * 2);
                ldsm4(a2[mt], Ab + 5120 + ((wm + mt * 16 + a_row) * 40 + c0 + a_col) * 2);
            }
            uint32_t b[4];
            const uint32_t boff = Ab + 10240 + ((wn + b_row) * 40 + c0 + b_col) * 2;
            // W2: r, z, i_n  (A1)
            ldsm4(b, boff);
#pragma unroll
            for (int mt = 0; mt < 2; mt++)
#pragma unroll
                for (int nt = 0; nt < 2; nt++) mma16816(aR[mt][nt], a1[mt], b[nt * 2], b[nt * 2 + 1]);
            ldsm4(b, boff + 2560);
#pragma unroll
            for (int mt = 0; mt < 2; mt++)
#pragma unroll
                for (int nt = 0; nt < 2; nt++) mma16816(aZ[mt][nt], a1[mt], b[nt * 2], b[nt * 2 + 1]);
            ldsm4(b, boff + 2 * 2560);
#pragma unroll
            for (int mt = 0; mt < 2; mt++)
#pragma unroll
                for (int nt = 0; nt < 2; nt++) mma16816(aI[mt][nt], a1[mt], b[nt * 2], b[nt * 2 + 1]);
            // W3: r, z, h_n  (A2)
            ldsm4(b, boff + 3 * 2560);
#pragma unroll
            for (int mt = 0; mt < 2; mt++)
#pragma unroll
                for (int nt = 0; nt < 2; nt++) mma16816(aR[mt][nt], a2[mt], b[nt * 2], b[nt * 2 + 1]);
            ldsm4(b, boff + 4 * 2560);
#pragma unroll
            for (int mt = 0; mt < 2; mt++)
#pragma unroll
                for (int nt = 0; nt < 2; nt++) mma16816(aZ[mt][nt], a2[mt], b[nt * 2], b[nt * 2 + 1]);
            ldsm4(b, boff + 5 * 2560);
#pragma unroll
            for (int mt = 0; mt < 2; mt++)
#pragma unroll
                for (int nt = 0; nt < 2; nt++) mma16816(aH[mt][nt], a2[mt], b[nt * 2], b[nt * 2 + 1]);
        }
        __syncthreads();
    }

    const int row = lane >> 2, colp = (lane & 3) * 2;
    const float* h2old = (t == 0) ? h2i : (g_H2 + (size_t)(t - 1) * B_ * H_);
    float* h2new = g_H2 + (size_t)t * B_ * H_;
    __nv_bfloat16* hc = g_H2c[newp];
#pragma unroll
    for (int mt = 0; mt < 2; mt++)
#pragma unroll
        for (int nt = 0; nt < 2; nt++) {
            int jg = j0 + wn + nt * 8 + colp;
            float2 br1 = *(const float2*)(bih + jg),        br2 = *(const float2*)(bhh + jg);
            float2 bz1 = *(const float2*)(bih + 512 + jg),  bz2 = *(const float2*)(bhh + 512 + jg);
            float2 bn1 = *(const float2*)(bih + 1024 + jg), bn2 = *(const float2*)(bhh + 1024 + jg);
#pragma unroll
            for (int hh = 0; hh < 2; hh++) {
                int m = m0 + wm + mt * 16 + row + hh * 8;
                float r0 = sigm(aR[mt][nt][hh * 2] + br1.x + br2.x);
                float r1 = sigm(aR[mt][nt][hh * 2 + 1] + br1.y + br2.y);
                float z0 = sigm(aZ[mt][nt][hh * 2] + bz1.x + bz2.x);
                float z1 = sigm(aZ[mt][nt][hh * 2 + 1] + bz1.y + bz2.y);
                float n0 = tanhf(aI[mt][nt][hh * 2] + bn1.x + r0 * (aH[mt][nt][hh * 2] + bn2.x));
                float n1 = tanhf(aI[mt][nt][hh * 2 + 1] + bn1.y + r1 * (aH[mt][nt][hh * 2 + 1] + bn2.y));
                float2 ho = *(const float2*)(h2old + (size_t)m * H_ + jg);
                float h0 = (1.f - z0) * n0 + z0 * ho.x;
                float h1 = (1.f - z1) * n1 + z1 * ho.y;
                *(float2*)(h2new + (size_t)m * H_ + jg) = make_float2(h0, h1);
                __nv_bfloat16 a0, l0, a1, l1;
                split2(h0, a0, l0); split2(h1, a1, l1);
                __nv_bfloat162 hv; hv.x = a0; hv.y = a1;
                __nv_bfloat162 lv; lv.x = l0; lv.y = l1;
                *(__nv_bfloat162*)(hc + (size_t)m * KC_ + jg) = hv;
                *(__nv_bfloat162*)(hc + (size_t)m * KC_ + 512 + jg) = hv;
                *(__nv_bfloat162*)(hc + (size_t)m * KC_ + 1024 + jg) = lv;
            }
        }
}

// ---------------------------------------------------------------------------
// k_fc: ys[b,t] = dot(h2[t][b], W_fc) + b_fc
// ---------------------------------------------------------------------------
__global__ __launch_bounds__(256) void k_fc(const float* __restrict__ Wfc,
                                            const float* __restrict__ bfc,
                                            float* __restrict__ out) {
    int w = (blockIdx.x * 256 + threadIdx.x) >> 5;
    int lane = threadIdx.x & 31;
    int b = w >> 6, tt = w & 63;
    const float* h = g_H2 + ((size_t)tt * B_ + b) * H_;
    float s = 0.f;
#pragma unroll
    for (int q = 0; q < H_ / 32; q++) s += h[lane + 32 * q] * Wfc[lane + 32 * q];
#pragma unroll
    for (int off = 16; off; off >>= 1) s += __shfl_down_sync(0xffffffffu, s, off);
    if (lane == 0) out[(size_t)b * L_ + tt] = s + bfc[0];
}

__global__ __launch_bounds__(256) void k_copy(float* __restrict__ out) {
    int i = blockIdx.x * 256 + threadIdx.x;
    const int n = B_ * H_;
    if (i < n) {
        out[B_ * L_ + i] = g_H1f[(L_ - 1) & 1][i];
        out[B_ * L_ + n + i] = g_H2[(size_t)(L_ - 1) * n + i];
    }
}

// ---------------------------------------------------------------------------
extern "C" void kernel_launch(void* const* d_in, const int* in_sizes, int n_in,
                              void* d_out, int out_size) {
    const float* x    = (const float*)d_in[0];
    const float* h1i  = (const float*)d_in[1];
    const float* h2i  = (const float*)d_in[2];
    const float* Wih1 = (const float*)d_in[3];
    const float* Whh1 = (const float*)d_in[4];
    const float* bih1 = (const float*)d_in[5];
    const float* bhh1 = (const float*)d_in[6];
    const float* Wih2 = (const float*)d_in[7];
    const float* Whh2 = (const float*)d_in[8];
    const float* bih2 = (const float*)d_in[9];
    const float* bhh2 = (const float*)d_in[10];
    const float* Wfc  = (const float*)d_in[11];
    const float* bfc  = (const float*)d_in[12];
    float* out = (float*)d_out;

    static bool attr_set = false;
    if (!attr_set) {
        cudaFuncSetAttribute(k_step2_tc, cudaFuncAttributeMaxDynamicSharedMemorySize, 51200);
        attr_set = true;
    }

    k_prep_w<<<(G3_ * H_ + 255) / 256, 256>>>(Wih1, Whh1, Wih2, Whh2);
    k_prep_h<<<(B_ * H_ + 255) / 256, 256>>>(h1i, h2i);
    k_prep_x<<<(L_ * B_ * H_ + 255) / 256, 256>>>(x);

    k_gi1_tc<<<dim3(8, 8, 64), 128, 40960>>>(bih1);

    for (int t = 0; t < L_; t++) {
        k_step1_tc<<<dim3(16, 8), 128, 25600>>>(t, bhh1);
        k_step2_tc<<<dim3(16, 8), 128, 51200>>>(t, h2i, bih2, bhh2);
    }

    k_fc<<<4096, 256>>>(Wfc, bfc, out);
    k_copy<<<(B_ * H_ + 255) / 256, 256>>>(out);
}

// round 4
// speedup vs baseline: 2.4325x; 2.4325x over previous
#include <cuda_runtime.h>
#include <cuda_bf16.h>
#include <math.h>
#include <stdint.h>

#define B_  512
#define T_  512
#define L_  64
#define H_  512
#define G3_ 1536
#define XW_ 575

// ------------------------- device scratch (no allocs) -----------------------
__device__ __align__(16) float g_GI1[(size_t)L_ * B_ * G3_];  // [t][b][3H]
__device__ __align__(16) float g_H1f[2][(size_t)B_ * H_];
__device__ __align__(16) float g_H2[(size_t)L_ * B_ * H_];    // fp32 h2 history
__device__ __align__(16) __nv_bfloat16 g_X2[(size_t)L_ * B_ * 1024]; // [t][b][hi 512 | lo 512]
__device__ __align__(16) __nv_bfloat16 g_W0h[(size_t)G3_ * H_], g_W0l[(size_t)G3_ * H_];
__device__ __align__(16) __nv_bfloat16 g_W1h[(size_t)G3_ * H_], g_W1l[(size_t)G3_ * H_];
__device__ __align__(16) __nv_bfloat16 g_W2h[(size_t)G3_ * H_], g_W2l[(size_t)G3_ * H_];
__device__ __align__(16) __nv_bfloat16 g_W3h[(size_t)G3_ * H_], g_W3l[(size_t)G3_ * H_];
__device__ __align__(16) __nv_bfloat16 g_H1h[2][(size_t)B_ * H_], g_H1l[2][(size_t)B_ * H_];
__device__ __align__(16) __nv_bfloat16 g_H2h[2][(size_t)B_ * H_], g_H2l[2][(size_t)B_ * H_];

__device__ __forceinline__ float sigm(float v) { return 1.f / (1.f + __expf(-v)); }

__device__ __forceinline__ uint32_t smem_u32(const void* p) {
    uint32_t a;
    asm("{ .reg .u64 t; cvta.to.shared.u64 t, %1; cvt.u32.u64 %0, t; }" : "=r"(a) : "l"(p));
    return a;
}
__device__ __forceinline__ void ldsm4(uint32_t* r, uint32_t addr) {
    asm volatile("ldmatrix.sync.aligned.m8n8.x4.shared.b16 {%0,%1,%2,%3}, [%4];"
                 : "=r"(r[0]), "=r"(r[1]), "=r"(r[2]), "=r"(r[3]) : "r"(addr));
}
__device__ __forceinline__ void mma16816(float* c, const uint32_t* a, uint32_t b0, uint32_t b1) {
    asm volatile("mma.sync.aligned.m16n8k16.row.col.f32.bf16.bf16.f32 "
                 "{%0,%1,%2,%3}, {%4,%5,%6,%7}, {%8,%9}, {%0,%1,%2,%3};"
                 : "+f"(c[0]), "+f"(c[1]), "+f"(c[2]), "+f"(c[3])
                 : "r"(a[0]), "r"(a[1]), "r"(a[2]), "r"(a[3]), "r"(b0), "r"(b1));
}
__device__ __forceinline__ void split2(float a, __nv_bfloat16& h, __nv_bfloat16& l) {
    h = __float2bfloat16_rn(a);
    l = __float2bfloat16_rn(a - __bfloat162float(h));
}
__device__ __forceinline__ void cp16(uint32_t dst, const void* src) {
    asm volatile("cp.async.cg.shared.global [%0], [%1], 16;" :: "r"(dst), "l"(src));
}
__device__ __forceinline__ void cp_commit() {
    asm volatile("cp.async.commit_group;" ::: "memory");
}
template <int N> __device__ __forceinline__ void cp_wait() {
    asm volatile("cp.async.wait_group %0;" :: "n"(N) : "memory");
}
// stage rows x 32 bf16 (64B) into pitch-80 smem via cp.async
__device__ __forceinline__ void stage_cp(uint32_t dst, const __nv_bfloat16* src,
                                         int rows, int stride, int tid) {
    for (int i = tid; i < rows * 4; i += 256) {
        int r = i >> 2, q = i & 3;
        cp16(dst + r * 80 + q * 16, src + (size_t)r * stride + q * 8);
    }
}

// ---------------------------------------------------------------------------
// Prep kernels
// ---------------------------------------------------------------------------
__global__ __launch_bounds__(256) void k_prep_w(const float* __restrict__ W0,
                                                const float* __restrict__ W1,
                                                const float* __restrict__ W2,
                                                const float* __restrict__ W3) {
    size_t i = (size_t)blockIdx.x * 256 + threadIdx.x;
    if (i >= (size_t)G3_ * H_) return;
    __nv_bfloat16 h, l;
    split2(W0[i], h, l); g_W0h[i] = h; g_W0l[i] = l;
    split2(W1[i], h, l); g_W1h[i] = h; g_W1l[i] = l;
    split2(W2[i], h, l); g_W2h[i] = h; g_W2l[i] = l;
    split2(W3[i], h, l); g_W3h[i] = h; g_W3l[i] = l;
}

__global__ __launch_bounds__(256) void k_prep_h(const float* __restrict__ h1i,
                                                const float* __restrict__ h2i) {
    size_t i = (size_t)blockIdx.x * 256 + threadIdx.x;
    if (i >= (size_t)B_ * H_) return;
    __nv_bfloat16 h, l;
    float a = h1i[i];
    split2(a, h, l); g_H1h[1][i] = h; g_H1l[1][i] = l; g_H1f[1][i] = a;
    split2(h2i[i], h, l); g_H2h[1][i] = h; g_H2l[1][i] = l;
}

__global__ __launch_bounds__(256) void k_prep_x(const float* __restrict__ x) {
    size_t i = (size_t)blockIdx.x * 256 + threadIdx.x;
    if (i >= (size_t)L_ * B_ * H_) return;
    int k = (int)(i % H_);
    int b = (int)((i / H_) % B_);
    int t = (int)(i / ((size_t)B_ * H_));
    __nv_bfloat16 h, l;
    split2(x[(size_t)b * XW_ + t + k], h, l);
    size_t o = ((size_t)t * B_ + b) * 1024;
    g_X2[o + k] = h; g_X2[o + 512 + k] = l;
}

// ---------------------------------------------------------------------------
// k_gi1_tc: GI1[t] = Xwin(t) @ W_ih1^T + b. M=128, N=3x64, K=512 (x3 terms).
// grid (8 j, 4 m, 64 t), 256 thr. buf 51200 x3 stages.
//   Ah@0 (128x80), Al@10240, Bh g@20480+g*5120, Bl g@35840+g*5120
// ---------------------------------------------------------------------------
__global__ __launch_bounds__(256, 1) void k_gi1_tc(const float* __restrict__ bias) {
    extern __shared__ char sm[];
    const uint32_t smb = smem_u32(sm);
    const int tid = threadIdx.x;
    const int j0 = blockIdx.x * 64;
    const int m0 = blockIdx.y * 128;
    const int t  = blockIdx.z;
    const __nv_bfloat16* A = g_X2 + ((size_t)t * B_ + m0) * 1024;

    auto stage = [&](int c) {
        const int k0 = c * 32;
        uint32_t d = smb + (uint32_t)(c % 3) * 51200;
        stage_cp(d,         A + k0,       128, 1024, tid);
        stage_cp(d + 10240, A + 512 + k0, 128, 1024, tid);
#pragma unroll
        for (int g = 0; g < 3; g++) {
            stage_cp(d + 20480 + g * 5120, g_W0h + (size_t)(g * 512 + j0) * H_ + k0, 64, H_, tid);
            stage_cp(d + 35840 + g * 5120, g_W0l + (size_t)(g * 512 + j0) * H_ + k0, 64, H_, tid);
        }
    };
    stage(0); cp_commit();
    stage(1); cp_commit();

    const int wid = tid >> 5, lane = tid & 31;
    const int wm = (wid >> 1) * 32, wnB = (wid & 1) * 32;
    const int arow = lane & 15, acol = (lane >> 4) * 8;
    const int brow = (lane & 7) + ((lane >> 4) << 3), bcol = ((lane >> 3) & 1) * 8;

    float acc[3][2][4][4];
#pragma unroll
    for (int g = 0; g < 3; g++)
#pragma unroll
        for (int mf = 0; mf < 2; mf++)
#pragma unroll
            for (int nf = 0; nf < 4; nf++)
#pragma unroll
                for (int q = 0; q < 4; q++) acc[g][mf][nf][q] = 0.f;

    for (int c = 0; c < 16; c++) {
        cp_wait<1>();
        __syncthreads();
        if (c + 2 < 16) stage(c + 2);
        cp_commit();
        const uint32_t Ab = smb + (uint32_t)(c % 3) * 51200;
#pragma unroll
        for (int h = 0; h < 2; h++) {
            const int c0 = h * 16;
            uint32_t aH[2][4], aL[2][4];
#pragma unroll
            for (int mf = 0; mf < 2; mf++) {
                uint32_t ao = ((wm + mf * 16 + arow) * 40 + c0 + acol) * 2;
                ldsm4(aH[mf], Ab + ao);
                ldsm4(aL[mf], Ab + 10240 + ao);
            }
#pragma unroll
            for (int g = 0; g < 3; g++) {
                uint32_t bh[2][4], bl[2][4];
#pragma unroll
                for (int np = 0; np < 2; np++) {
                    uint32_t bo = ((wnB + np * 16 + brow) * 40 + c0 + bcol) * 2;
                    ldsm4(bh[np], Ab + 20480 + g * 5120 + bo);
                    ldsm4(bl[np], Ab + 35840 + g * 5120 + bo);
                }
#pragma unroll
                for (int mf = 0; mf < 2; mf++)
#pragma unroll
                    for (int np = 0; np < 2; np++)
#pragma unroll
                        for (int hf = 0; hf < 2; hf++) {
                            float* a = acc[g][mf][np * 2 + hf];
                            mma16816(a, aH[mf], bh[np][hf * 2], bh[np][hf * 2 + 1]);
                            mma16816(a, aH[mf], bl[np][hf * 2], bl[np][hf * 2 + 1]);
                            mma16816(a, aL[mf], bh[np][hf * 2], bh[np][hf * 2 + 1]);
                        }
            }
        }
    }

    const int row = lane >> 2, colp = (lane & 3) * 2;
    float* gi = g_GI1 + ((size_t)t * B_ + m0) * G3_;
#pragma unroll
    for (int g = 0; g < 3; g++)
#pragma unroll
        for (int mf = 0; mf < 2; mf++)
#pragma unroll
            for (int nf = 0; nf < 4; nf++) {
                int jg = j0 + wnB + (nf >> 1) * 16 + (nf & 1) * 8 + colp;
                float2 bv = *(const float2*)(bias + g * 512 + jg);
#pragma unroll
                for (int hh = 0; hh < 2; hh++) {
                    int m = wm + mf * 16 + row + hh * 8;
                    float2 o;
                    o.x = acc[g][mf][nf][hh * 2 + 0] + bv.x;
                    o.y = acc[g][mf][nf][hh * 2 + 1] + bv.y;
                    *(float2*)(gi + (size_t)m * G3_ + g * 512 + jg) = o;
                }
            }
}

// ---------------------------------------------------------------------------
// k_step1_tc: h1' = GRU1(gi1[t], h1). M=64, N=3x32, K=512 (x3 terms).
// grid (16 j, 8 m), 256 thr. buf 25600 x3.
//   Ah@0 (64x80), Al@5120, Bh g@10240+g*2560, Bl g@17920+g*2560
// ---------------------------------------------------------------------------
__global__ __launch_bounds__(256, 1) void k_step1_tc(int t, const float* __restrict__ bhh) {
    extern __shared__ char sm[];
    const uint32_t smb = smem_u32(sm);
    const int tid = threadIdx.x;
    const int j0 = blockIdx.x * 32;
    const int m0 = blockIdx.y * 64;
    const int oldp = (t + 1) & 1, newp = t & 1;
    const __nv_bfloat16* Ah = g_H1h[oldp] + (size_t)m0 * H_;
    const __nv_bfloat16* Al = g_H1l[oldp] + (size_t)m0 * H_;

    auto stage = [&](int c) {
        const int k0 = c * 32;
        uint32_t d = smb + (uint32_t)(c % 3) * 25600;
        stage_cp(d,        Ah + k0, 64, H_, tid);
        stage_cp(d + 5120, Al + k0, 64, H_, tid);
#pragma unroll
        for (int g = 0; g < 3; g++) {
            stage_cp(d + 10240 + g * 2560, g_W1h + (size_t)(g * 512 + j0) * H_ + k0, 32, H_, tid);
            stage_cp(d + 17920 + g * 2560, g_W1l + (size_t)(g * 512 + j0) * H_ + k0, 32, H_, tid);
        }
    };
    stage(0); cp_commit();
    stage(1); cp_commit();

    const int wid = tid >> 5, lane = tid & 31;
    const int wm = (wid >> 1) * 16, wnB = (wid & 1) * 16;
    const int arow = lane & 15, acol = (lane >> 4) * 8;
    const int brow = (lane & 7) + ((lane >> 4) << 3), bcol = ((lane >> 3) & 1) * 8;

    float acc[3][2][4];
#pragma unroll
    for (int g = 0; g < 3; g++)
#pragma unroll
        for (int nf = 0; nf < 2; nf++)
#pragma unroll
            for (int q = 0; q < 4; q++) acc[g][nf][q] = 0.f;

    for (int c = 0; c < 16; c++) {
        cp_wait<1>();
        __syncthreads();
        if (c + 2 < 16) stage(c + 2);
        cp_commit();
        const uint32_t Ab = smb + (uint32_t)(c % 3) * 25600;
#pragma unroll
        for (int h = 0; h < 2; h++) {
            const int c0 = h * 16;
            uint32_t aH[4], aL[4];
            uint32_t ao = ((wm + arow) * 40 + c0 + acol) * 2;
            ldsm4(aH, Ab + ao);
            ldsm4(aL, Ab + 5120 + ao);
            uint32_t bo = ((wnB + brow) * 40 + c0 + bcol) * 2;
#pragma unroll
            for (int g = 0; g < 3; g++) {
                uint32_t bh[4], bl[4];
                ldsm4(bh, Ab + 10240 + g * 2560 + bo);
                ldsm4(bl, Ab + 17920 + g * 2560 + bo);
#pragma unroll
                for (int nf = 0; nf < 2; nf++) {
                    mma16816(acc[g][nf], aH, bh[nf * 2], bh[nf * 2 + 1]);
                    mma16816(acc[g][nf], aH, bl[nf * 2], bl[nf * 2 + 1]);
                    mma16816(acc[g][nf], aL, bh[nf * 2], bh[nf * 2 + 1]);
                }
            }
        }
    }

    const int row = lane >> 2, colp = (lane & 3) * 2;
    const float* hfO = g_H1f[oldp];
    float* hfN = g_H1f[newp];
    __nv_bfloat16* hhN = g_H1h[newp];
    __nv_bfloat16* hlN = g_H1l[newp];
#pragma unroll
    for (int nf = 0; nf < 2; nf++) {
        int jg = j0 + wnB + nf * 8 + colp;
        float2 br = *(const float2*)(bhh + jg);
        float2 bz = *(const float2*)(bhh + 512 + jg);
        float2 bn = *(const float2*)(bhh + 1024 + jg);
#pragma unroll
        for (int hh = 0; hh < 2; hh++) {
            int m = m0 + wm + row + hh * 8;
            const float* gi = g_GI1 + ((size_t)t * B_ + m) * G3_;
            float2 gr = *(const float2*)(gi + jg);
            float2 gz = *(const float2*)(gi + 512 + jg);
            float2 gn = *(const float2*)(gi + 1024 + jg);
            float r0 = sigm(gr.x + acc[0][nf][hh * 2] + br.x);
            float r1 = sigm(gr.y + acc[0][nf][hh * 2 + 1] + br.y);
            float z0 = sigm(gz.x + acc[1][nf][hh * 2] + bz.x);
            float z1 = sigm(gz.y + acc[1][nf][hh * 2 + 1] + bz.y);
            float n0 = tanhf(gn.x + r0 * (acc[2][nf][hh * 2] + bn.x));
            float n1 = tanhf(gn.y + r1 * (acc[2][nf][hh * 2 + 1] + bn.y));
            float2 ho = *(const float2*)(hfO + (size_t)m * H_ + jg);
            float h0 = (1.f - z0) * n0 + z0 * ho.x;
            float h1 = (1.f - z1) * n1 + z1 * ho.y;
            *(float2*)(hfN + (size_t)m * H_ + jg) = make_float2(h0, h1);
            __nv_bfloat16 x0, y0, x1, y1;
            split2(h0, x0, y0); split2(h1, x1, y1);
            __nv_bfloat162 hv; hv.x = x0; hv.y = x1;
            __nv_bfloat162 lv; lv.x = y0; lv.y = y1;
            *(__nv_bfloat162*)(hhN + (size_t)m * H_ + jg) = hv;
            *(__nv_bfloat162*)(hlN + (size_t)m * H_ + jg) = lv;
        }
    }
}

// ---------------------------------------------------------------------------
// k_step2_tc: h2' = GRU2(h1', h2). Two matmuls; r/z accumulate both.
// M=64, N=3x32. grid (16, 8), 256 thr. buf 51200 x3.
//   A1h@0, A1l@5120, A2h@10240, A2l@15360,
//   W2h g@20480+g*2560, W2l @28160+, W3h @35840+, W3l @43520+
// ---------------------------------------------------------------------------
__global__ __launch_bounds__(256, 1) void k_step2_tc(int t, const float* __restrict__ h2i,
                                                     const float* __restrict__ bih,
                                                     const float* __restrict__ bhh) {
    extern __shared__ char sm[];
    const uint32_t smb = smem_u32(sm);
    const int tid = threadIdx.x;
    const int j0 = blockIdx.x * 32;
    const int m0 = blockIdx.y * 64;
    const int oldp = (t + 1) & 1, newp = t & 1;
    const __nv_bfloat16* A1h = g_H1h[newp] + (size_t)m0 * H_;
    const __nv_bfloat16* A1l = g_H1l[newp] + (size_t)m0 * H_;
    const __nv_bfloat16* A2h = g_H2h[oldp] + (size_t)m0 * H_;
    const __nv_bfloat16* A2l = g_H2l[oldp] + (size_t)m0 * H_;

    auto stage = [&](int c) {
        const int k0 = c * 32;
        uint32_t d = smb + (uint32_t)(c % 3) * 51200;
        stage_cp(d,         A1h + k0, 64, H_, tid);
        stage_cp(d + 5120,  A1l + k0, 64, H_, tid);
        stage_cp(d + 10240, A2h + k0, 64, H_, tid);
        stage_cp(d + 15360, A2l + k0, 64, H_, tid);
#pragma unroll
        for (int g = 0; g < 3; g++) {
            const size_t wo = (size_t)(g * 512 + j0) * H_ + k0;
            stage_cp(d + 20480 + g * 2560, g_W2h + wo, 32, H_, tid);
            stage_cp(d + 28160 + g * 2560, g_W2l + wo, 32, H_, tid);
            stage_cp(d + 35840 + g * 2560, g_W3h + wo, 32, H_, tid);
            stage_cp(d + 43520 + g * 2560, g_W3l + wo, 32, H_, tid);
        }
    };
    stage(0); cp_commit();
    stage(1); cp_commit();

    const int wid = tid >> 5, lane = tid & 31;
    const int wm = (wid >> 1) * 16, wnB = (wid & 1) * 16;
    const int arow = lane & 15, acol = (lane >> 4) * 8;
    const int brow = (lane & 7) + ((lane >> 4) << 3), bcol = ((lane >> 3) & 1) * 8;

    float aR[2][4], aZ[2][4], aI[2][4], aN[2][4];
#pragma unroll
    for (int nf = 0; nf < 2; nf++)
#pragma unroll
        for (int q = 0; q < 4; q++) {
            aR[nf][q] = 0.f; aZ[nf][q] = 0.f; aI[nf][q] = 0.f; aN[nf][q] = 0.f;
        }

    for (int c = 0; c < 16; c++) {
        cp_wait<1>();
        __syncthreads();
        if (c + 2 < 16) stage(c + 2);
        cp_commit();
        const uint32_t Ab = smb + (uint32_t)(c % 3) * 51200;
#pragma unroll
        for (int h = 0; h < 2; h++) {
            const int c0 = h * 16;
            uint32_t a1H[4], a1L[4], a2H[4], a2L[4];
            uint32_t ao = ((wm + arow) * 40 + c0 + acol) * 2;
            ldsm4(a1H, Ab + ao);
            ldsm4(a1L, Ab + 5120 + ao);
            ldsm4(a2H, Ab + 10240 + ao);
            ldsm4(a2L, Ab + 15360 + ao);
            uint32_t bo = ((wnB + brow) * 40 + c0 + bcol) * 2;
#pragma unroll
            for (int g = 0; g < 3; g++) {
                uint32_t w2h[4], w2l[4], w3h[4], w3l[4];
                ldsm4(w2h, Ab + 20480 + g * 2560 + bo);
                ldsm4(w2l, Ab + 28160 + g * 2560 + bo);
                ldsm4(w3h, Ab + 35840 + g * 2560 + bo);
                ldsm4(w3l, Ab + 43520 + g * 2560 + bo);
                float (*c1)[4] = (g == 0) ? aR : (g == 1) ? aZ : aI;
                float (*c2)[4] = (g == 0) ? aR : (g == 1) ? aZ : aN;
#pragma unroll
                for (int nf = 0; nf < 2; nf++) {
                    mma16816(c1[nf], a1H, w2h[nf * 2], w2h[nf * 2 + 1]);
                    mma16816(c1[nf], a1H, w2l[nf * 2], w2l[nf * 2 + 1]);
                    mma16816(c1[nf], a1L, w2h[nf * 2], w2h[nf * 2 + 1]);
                    mma16816(c2[nf], a2H, w3h[nf * 2], w3h[nf * 2 + 1]);
                    mma16816(c2[nf], a2H, w3l[nf * 2], w3l[nf * 2 + 1]);
                    mma16816(c2[nf], a2L, w3h[nf * 2], w3h[nf * 2 + 1]);
                }
            }
        }
    }

    const int row = lane >> 2, colp = (lane & 3) * 2;
    const float* h2old = (t == 0) ? h2i : (g_H2 + (size_t)(t - 1) * B_ * H_);
    float* h2new = g_H2 + (size_t)t * B_ * H_;
    __nv_bfloat16* hhN = g_H2h[newp];
    __nv_bfloat16* hlN = g_H2l[newp];
#pragma unroll
    for (int nf = 0; nf < 2; nf++) {
        int jg = j0 + wnB + nf * 8 + colp;
        float2 br1 = *(const float2*)(bih + jg),        br2 = *(const float2*)(bhh + jg);
        float2 bz1 = *(const float2*)(bih + 512 + jg),  bz2 = *(const float2*)(bhh + 512 + jg);
        float2 bn1 = *(const float2*)(bih + 1024 + jg), bn2 = *(const float2*)(bhh + 1024 + jg);
#pragma unroll
        for (int hh = 0; hh < 2; hh++) {
            int m = m0 + wm + row + hh * 8;
            float r0 = sigm(aR[nf][hh * 2] + br1.x + br2.x);
            float r1 = sigm(aR[nf][hh * 2 + 1] + br1.y + br2.y);
            float z0 = sigm(aZ[nf][hh * 2] + bz1.x + bz2.x);
            float z1 = sigm(aZ[nf][hh * 2 + 1] + bz1.y + bz2.y);
            float n0 = tanhf(aI[nf][hh * 2] + bn1.x + r0 * (aN[nf][hh * 2] + bn2.x));
            float n1 = tanhf(aI[nf][hh * 2 + 1] + bn1.y + r1 * (aN[nf][hh * 2 + 1] + bn2.y));
            float2 ho = *(const float2*)(h2old + (size_t)m * H_ + jg);
            float h0 = (1.f - z0) * n0 + z0 * ho.x;
            float h1 = (1.f - z1) * n1 + z1 * ho.y;
            *(float2*)(h2new + (size_t)m * H_ + jg) = make_float2(h0, h1);
            __nv_bfloat16 x0, y0, x1, y1;
            split2(h0, x0, y0); split2(h1, x1, y1);
            __nv_bfloat162 hv; hv.x = x0; hv.y = x1;
            __nv_bfloat162 lv; lv.x = y0; lv.y = y1;
            *(__nv_bfloat162*)(hhN + (size_t)m * H_ + jg) = hv;
            *(__nv_bfloat162*)(hlN + (size_t)m * H_ + jg) = lv;
        }
    }
}

// ---------------------------------------------------------------------------
__global__ __launch_bounds__(256) void k_fc(const float* __restrict__ Wfc,
                                            const float* __restrict__ bfc,
                                            float* __restrict__ out) {
    int w = (blockIdx.x * 256 + threadIdx.x) >> 5;
    int lane = threadIdx.x & 31;
    int b = w >> 6, tt = w & 63;
    const float* h = g_H2 + ((size_t)tt * B_ + b) * H_;
    float s = 0.f;
#pragma unroll
    for (int q = 0; q < H_ / 32; q++) s += h[lane + 32 * q] * Wfc[lane + 32 * q];
#pragma unroll
    for (int off = 16; off; off >>= 1) s += __shfl_down_sync(0xffffffffu, s, off);
    if (lane == 0) out[(size_t)b * L_ + tt] = s + bfc[0];
}

__global__ __launch_bounds__(256) void k_copy(float* __restrict__ out) {
    int i = blockIdx.x * 256 + threadIdx.x;
    const int n = B_ * H_;
    if (i < n) {
        out[B_ * L_ + i] = g_H1f[(L_ - 1) & 1][i];
        out[B_ * L_ + n + i] = g_H2[(size_t)(L_ - 1) * n + i];
    }
}

// ---------------------------------------------------------------------------
extern "C" void kernel_launch(void* const* d_in, const int* in_sizes, int n_in,
                              void* d_out, int out_size) {
    const float* x    = (const float*)d_in[0];
    const float* h1i  = (const float*)d_in[1];
    const float* h2i  = (const float*)d_in[2];
    const float* Wih1 = (const float*)d_in[3];
    const float* Whh1 = (const float*)d_in[4];
    const float* bih1 = (const float*)d_in[5];
    const float* bhh1 = (const float*)d_in[6];
    const float* Wih2 = (const float*)d_in[7];
    const float* Whh2 = (const float*)d_in[8];
    const float* bih2 = (const float*)d_in[9];
    const float* bhh2 = (const float*)d_in[10];
    const float* Wfc  = (const float*)d_in[11];
    const float* bfc  = (const float*)d_in[12];
    float* out = (float*)d_out;

    cudaFuncSetAttribute(k_gi1_tc,  cudaFuncAttributeMaxDynamicSharedMemorySize, 153600);
    cudaFuncSetAttribute(k_step1_tc, cudaFuncAttributeMaxDynamicSharedMemorySize, 76800);
    cudaFuncSetAttribute(k_step2_tc, cudaFuncAttributeMaxDynamicSharedMemorySize, 153600);

    k_prep_w<<<(G3_ * H_ + 255) / 256, 256>>>(Wih1, Whh1, Wih2, Whh2);
    k_prep_h<<<(B_ * H_ + 255) / 256, 256>>>(h1i, h2i);
    k_prep_x<<<(L_ * B_ * H_ + 255) / 256, 256>>>(x);

    k_gi1_tc<<<dim3(8, 4, 64), 256, 153600>>>(bih1);

    for (int t = 0; t < L_; t++) {
        k_step1_tc<<<dim3(16, 8), 256, 76800>>>(t, bhh1);
        k_step2_tc<<<dim3(16, 8), 256, 153600>>>(t, h2i, bih2, bhh2);
    }

    k_fc<<<4096, 256>>>(Wfc, bfc, out);
    k_copy<<<(B_ * H_ + 255) / 256, 256>>>(out);
}

// round 5
// speedup vs baseline: 3.8323x; 1.5755x over previous
#include <cuda_runtime.h>
#include <cuda_bf16.h>
#include <math.h>
#include <stdint.h>

#define B_  512
#define T_  512
#define L_  64
#define H_  512
#define G3_ 1536
#define XW_ 575

// ------------------------- device scratch (no allocs) -----------------------
__device__ __align__(16) float g_GI1[(size_t)L_ * B_ * G3_];  // [t][b][3H]
__device__ __align__(16) float g_H1fin[(size_t)B_ * H_];      // final h1 (t=63)
__device__ __align__(16) float g_H2[(size_t)L_ * B_ * H_];    // fp32 h2 history
__device__ __align__(16) __nv_bfloat16 g_X2[(size_t)L_ * B_ * 1024]; // [t][b][hi|lo]
__device__ __align__(16) __nv_bfloat16 g_W0h[(size_t)G3_ * H_], g_W0l[(size_t)G3_ * H_];
__device__ __align__(16) __nv_bfloat16 g_W1h[(size_t)G3_ * H_], g_W1l[(size_t)G3_ * H_];
__device__ __align__(16) __nv_bfloat16 g_W2h[(size_t)G3_ * H_], g_W2l[(size_t)G3_ * H_];
__device__ __align__(16) __nv_bfloat16 g_W3h[(size_t)G3_ * H_], g_W3l[(size_t)G3_ * H_];
__device__ __align__(16) __nv_bfloat16 g_H1h[2][(size_t)B_ * H_], g_H1l[2][(size_t)B_ * H_];
__device__ __align__(16) __nv_bfloat16 g_H2h[2][(size_t)B_ * H_], g_H2l[2][(size_t)B_ * H_];
__device__ unsigned g_bar;   // grid barrier counter (memset to 0 per launch)

__device__ __forceinline__ float sigm(float v) { return 1.f / (1.f + __expf(-v)); }

__device__ __forceinline__ uint32_t smem_u32(const void* p) {
    uint32_t a;
    asm("{ .reg .u64 t; cvta.to.shared.u64 t, %1; cvt.u32.u64 %0, t; }" : "=r"(a) : "l"(p));
    return a;
}
__device__ __forceinline__ void ldsm4(uint32_t* r, uint32_t addr) {
    asm volatile("ldmatrix.sync.aligned.m8n8.x4.shared.b16 {%0,%1,%2,%3}, [%4];"
                 : "=r"(r[0]), "=r"(r[1]), "=r"(r[2]), "=r"(r[3]) : "r"(addr));
}
__device__ __forceinline__ void mma16816(float* c, const uint32_t* a, uint32_t b0, uint32_t b1) {
    asm volatile("mma.sync.aligned.m16n8k16.row.col.f32.bf16.bf16.f32 "
                 "{%0,%1,%2,%3}, {%4,%5,%6,%7}, {%8,%9}, {%0,%1,%2,%3};"
                 : "+f"(c[0]), "+f"(c[1]), "+f"(c[2]), "+f"(c[3])
                 : "r"(a[0]), "r"(a[1]), "r"(a[2]), "r"(a[3]), "r"(b0), "r"(b1));
}
__device__ __forceinline__ void split2(float a, __nv_bfloat16& h, __nv_bfloat16& l) {
    h = __float2bfloat16_rn(a);
    l = __float2bfloat16_rn(a - __bfloat162float(h));
}
__device__ __forceinline__ void cp16(uint32_t dst, const void* src) {
    asm volatile("cp.async.cg.shared.global [%0], [%1], 16;" :: "r"(dst), "l"(src));
}
__device__ __forceinline__ void cp_commit() {
    asm volatile("cp.async.commit_group;" ::: "memory");
}
template <int N> __device__ __forceinline__ void cp_wait() {
    asm volatile("cp.async.wait_group %0;" :: "n"(N) : "memory");
}
__device__ __forceinline__ void stage_cp(uint32_t dst, const __nv_bfloat16* src,
                                         int rows, int stride, int tid, int nthr) {
    for (int i = tid; i < rows * 4; i += nthr) {
        int r = i >> 2, q = i & 3;
        cp16(dst + r * 80 + q * 16, src + (size_t)r * stride + q * 8);
    }
}
// grid barrier: monotone counter, all-thread release fence, tid0 arrive+poll
__device__ __forceinline__ void gridbar(unsigned target) {
    __threadfence();
    __syncthreads();
    if (threadIdx.x == 0) {
        atomicAdd(&g_bar, 1u);
        while (*(volatile unsigned*)&g_bar < target) { }
    }
    __syncthreads();
}

// ---------------------------------------------------------------------------
// Prep kernels
// ---------------------------------------------------------------------------
__global__ __launch_bounds__(256) void k_prep_w(const float* __restrict__ W0,
                                                const float* __restrict__ W1,
                                                const float* __restrict__ W2,
                                                const float* __restrict__ W3) {
    size_t i = (size_t)blockIdx.x * 256 + threadIdx.x;
    if (i >= (size_t)G3_ * H_) return;
    __nv_bfloat16 h, l;
    split2(W0[i], h, l); g_W0h[i] = h; g_W0l[i] = l;
    split2(W1[i], h, l); g_W1h[i] = h; g_W1l[i] = l;
    split2(W2[i], h, l); g_W2h[i] = h; g_W2l[i] = l;
    split2(W3[i], h, l); g_W3h[i] = h; g_W3l[i] = l;
}

__global__ __launch_bounds__(256) void k_prep_h(const float* __restrict__ h1i,
                                                const float* __restrict__ h2i) {
    size_t i = (size_t)blockIdx.x * 256 + threadIdx.x;
    if (i >= (size_t)B_ * H_) return;
    __nv_bfloat16 h, l;
    split2(h1i[i], h, l); g_H1h[1][i] = h; g_H1l[1][i] = l;
    split2(h2i[i], h, l); g_H2h[1][i] = h; g_H2l[1][i] = l;
}

__global__ __launch_bounds__(256) void k_prep_x(const float* __restrict__ x) {
    size_t i = (size_t)blockIdx.x * 256 + threadIdx.x;
    if (i >= (size_t)L_ * B_ * H_) return;
    int k = (int)(i % H_);
    int b = (int)((i / H_) % B_);
    int t = (int)(i / ((size_t)B_ * H_));
    __nv_bfloat16 h, l;
    split2(x[(size_t)b * XW_ + t + k], h, l);
    size_t o = ((size_t)t * B_ + b) * 1024;
    g_X2[o + k] = h; g_X2[o + 512 + k] = l;
}

// ---------------------------------------------------------------------------
// k_gi1_tc: GI1[t] = Xwin(t) @ W_ih1^T + b. M=128, N=3x64, K=512 (x3 terms).
// grid (8 j, 4 m, 64 t), 512 thr (16 warps: 4m x 4n). 3-stage cp.async.
//   Ah@0 (128x80), Al@10240, Bh g@20480+g*5120, Bl g@35840+g*5120; stage=51200
// ---------------------------------------------------------------------------
__global__ __launch_bounds__(512, 1) void k_gi1_tc(const float* __restrict__ bias) {
    extern __shared__ char sm[];
    const uint32_t smb = smem_u32(sm);
    const int tid = threadIdx.x;
    const int j0 = blockIdx.x * 64;
    const int m0 = blockIdx.y * 128;
    const int t  = blockIdx.z;
    const __nv_bfloat16* A = g_X2 + ((size_t)t * B_ + m0) * 1024;

    auto stage = [&](int c) {
        const int k0 = c * 32;
        uint32_t d = smb + (uint32_t)(c % 3) * 51200;
        stage_cp(d,         A + k0,       128, 1024, tid, 512);
        stage_cp(d + 10240, A + 512 + k0, 128, 1024, tid, 512);
#pragma unroll
        for (int g = 0; g < 3; g++) {
            stage_cp(d + 20480 + g * 5120, g_W0h + (size_t)(g * 512 + j0) * H_ + k0, 64, H_, tid, 512);
            stage_cp(d + 35840 + g * 5120, g_W0l + (size_t)(g * 512 + j0) * H_ + k0, 64, H_, tid, 512);
        }
    };
    stage(0); cp_commit();
    stage(1); cp_commit();

    const int wid = tid >> 5, lane = tid & 31;
    const int wm = (wid >> 2) * 32;       // 4 m groups of 32 rows
    const int wn = (wid & 3) * 16;        // per-gate 16-col offset
    const int arow = lane & 15, acol = (lane >> 4) * 8;
    const int brow = (lane & 7) + ((lane >> 4) << 3), bcol = ((lane >> 3) & 1) * 8;

    float acc[3][2][2][4];
#pragma unroll
    for (int g = 0; g < 3; g++)
#pragma unroll
        for (int mf = 0; mf < 2; mf++)
#pragma unroll
            for (int nf = 0; nf < 2; nf++)
#pragma unroll
                for (int q = 0; q < 4; q++) acc[g][mf][nf][q] = 0.f;

    for (int c = 0; c < 16; c++) {
        cp_wait<1>();
        __syncthreads();
        if (c + 2 < 16) stage(c + 2);
        cp_commit();
        const uint32_t Ab = smb + (uint32_t)(c % 3) * 51200;
#pragma unroll
        for (int h = 0; h < 2; h++) {
            const int c0 = h * 16;
            uint32_t aH[2][4], aL[2][4];
#pragma unroll
            for (int mf = 0; mf < 2; mf++) {
                uint32_t ao = ((wm + mf * 16 + arow) * 40 + c0 + acol) * 2;
                ldsm4(aH[mf], Ab + ao);
                ldsm4(aL[mf], Ab + 10240 + ao);
            }
            uint32_t bo = ((wn + brow) * 40 + c0 + bcol) * 2;
#pragma unroll
            for (int g = 0; g < 3; g++) {
                uint32_t bh[4], bl[4];
                ldsm4(bh, Ab + 20480 + g * 5120 + bo);
                ldsm4(bl, Ab + 35840 + g * 5120 + bo);
#pragma unroll
                for (int mf = 0; mf < 2; mf++)
#pragma unroll
                    for (int nf = 0; nf < 2; nf++) {
                        float* a = acc[g][mf][nf];
                        mma16816(a, aH[mf], bh[nf * 2], bh[nf * 2 + 1]);
                        mma16816(a, aH[mf], bl[nf * 2], bl[nf * 2 + 1]);
                        mma16816(a, aL[mf], bh[nf * 2], bh[nf * 2 + 1]);
                    }
            }
        }
    }

    const int row = lane >> 2, colp = (lane & 3) * 2;
    float* gi = g_GI1 + ((size_t)t * B_ + m0) * G3_;
#pragma unroll
    for (int g = 0; g < 3; g++)
#pragma unroll
        for (int mf = 0; mf < 2; mf++)
#pragma unroll
            for (int nf = 0; nf < 2; nf++) {
                int jg = j0 + wn + nf * 8 + colp;
                float2 bv = *(const float2*)(bias + g * 512 + jg);
#pragma unroll
                for (int hh = 0; hh < 2; hh++) {
                    int m = wm + mf * 16 + row + hh * 8;
                    float2 o;
                    o.x = acc[g][mf][nf][hh * 2 + 0] + bv.x;
                    o.y = acc[g][mf][nf][hh * 2 + 1] + bv.y;
                    *(float2*)(gi + (size_t)m * G3_ + g * 512 + jg) = o;
                }
            }
}

// ---------------------------------------------------------------------------
// k_steps: persistent 2-layer GRU recurrence, 64 steps, 128 CTAs (1/SM),
// 256 threads. Per step: phase A (layer 1), gridbar, phase B (layer 2), gridbar.
// CTA tile fixed for all t: j0=(bid&15)*32, m0=(bid>>4)*64.
// smem: phase A 3x25600, phase B 3x51200 (max 153600).
// h(t-1) at this thread's output coords carried in registers.
// ---------------------------------------------------------------------------
__global__ __launch_bounds__(256, 1) void k_steps(const float* __restrict__ h1i,
                                                  const float* __restrict__ h2i,
                                                  const float* __restrict__ bhh1,
                                                  const float* __restrict__ bih2,
                                                  const float* __restrict__ bhh2) {
    extern __shared__ char sm[];
    const uint32_t smb = smem_u32(sm);
    const int tid = threadIdx.x;
    const int bid = blockIdx.x;
    const int j0 = (bid & 15) * 32;
    const int m0 = (bid >> 4) * 64;
    const int wid = tid >> 5, lane = tid & 31;
    const int wm = (wid >> 1) * 16, wnB = (wid & 1) * 16;
    const int arow = lane & 15, acol = (lane >> 4) * 8;
    const int brow = (lane & 7) + ((lane >> 4) << 3), bcol = ((lane >> 3) & 1) * 8;
    const int row = lane >> 2, colp = (lane & 3) * 2;

    // preload biases + initial hidden state (registers, fixed coords)
    float2 a_br[2], a_bz[2], a_bn[2];
    float2 b_br[2], b_bz[2], b_bn1[2], b_bn2[2];
    float2 h1p[2][2], h2p[2][2];
#pragma unroll
    for (int nf = 0; nf < 2; nf++) {
        int jg = j0 + wnB + nf * 8 + colp;
        a_br[nf] = *(const float2*)(bhh1 + jg);
        a_bz[nf] = *(const float2*)(bhh1 + 512 + jg);
        a_bn[nf] = *(const float2*)(bhh1 + 1024 + jg);
        float2 u, v;
        u = *(const float2*)(bih2 + jg);        v = *(const float2*)(bhh2 + jg);
        b_br[nf] = make_float2(u.x + v.x, u.y + v.y);
        u = *(const float2*)(bih2 + 512 + jg);  v = *(const float2*)(bhh2 + 512 + jg);
        b_bz[nf] = make_float2(u.x + v.x, u.y + v.y);
        b_bn1[nf] = *(const float2*)(bih2 + 1024 + jg);
        b_bn2[nf] = *(const float2*)(bhh2 + 1024 + jg);
#pragma unroll
        for (int hh = 0; hh < 2; hh++) {
            int m = m0 + wm + row + hh * 8;
            h1p[nf][hh] = *(const float2*)(h1i + (size_t)m * H_ + jg);
            h2p[nf][hh] = *(const float2*)(h2i + (size_t)m * H_ + jg);
        }
    }

    unsigned bar_t = 0;
    for (int t = 0; t < L_; t++) {
        const int oldp = (t + 1) & 1, newp = t & 1;

        // ================= phase A: layer-1 GRU =================
        {
            const __nv_bfloat16* Ah = g_H1h[oldp] + (size_t)m0 * H_;
            const __nv_bfloat16* Al = g_H1l[oldp] + (size_t)m0 * H_;
            auto stage = [&](int c) {
                const int k0 = c * 32;
                uint32_t d = smb + (uint32_t)(c % 3) * 25600;
                stage_cp(d,        Ah + k0, 64, H_, tid, 256);
                stage_cp(d + 5120, Al + k0, 64, H_, tid, 256);
#pragma unroll
                for (int g = 0; g < 3; g++) {
                    stage_cp(d + 10240 + g * 2560, g_W1h + (size_t)(g * 512 + j0) * H_ + c * 32, 32, H_, tid, 256);
                    stage_cp(d + 17920 + g * 2560, g_W1l + (size_t)(g * 512 + j0) * H_ + c * 32, 32, H_, tid, 256);
                }
            };
            stage(0); cp_commit();
            stage(1); cp_commit();

            float acc[3][2][4];
#pragma unroll
            for (int g = 0; g < 3; g++)
#pragma unroll
                for (int nf = 0; nf < 2; nf++)
#pragma unroll
                    for (int q = 0; q < 4; q++) acc[g][nf][q] = 0.f;

            for (int c = 0; c < 16; c++) {
                cp_wait<1>();
                __syncthreads();
                if (c + 2 < 16) stage(c + 2);
                cp_commit();
                const uint32_t Ab = smb + (uint32_t)(c % 3) * 25600;
#pragma unroll
                for (int h = 0; h < 2; h++) {
                    const int c0 = h * 16;
                    uint32_t aH[4], aL[4];
                    uint32_t ao = ((wm + arow) * 40 + c0 + acol) * 2;
                    ldsm4(aH, Ab + ao);
                    ldsm4(aL, Ab + 5120 + ao);
                    uint32_t bo = ((wnB + brow) * 40 + c0 + bcol) * 2;
#pragma unroll
                    for (int g = 0; g < 3; g++) {
                        uint32_t bh[4], bl[4];
                        ldsm4(bh, Ab + 10240 + g * 2560 + bo);
                        ldsm4(bl, Ab + 17920 + g * 2560 + bo);
#pragma unroll
                        for (int nf = 0; nf < 2; nf++) {
                            mma16816(acc[g][nf], aH, bh[nf * 2], bh[nf * 2 + 1]);
                            mma16816(acc[g][nf], aH, bl[nf * 2], bl[nf * 2 + 1]);
                            mma16816(acc[g][nf], aL, bh[nf * 2], bh[nf * 2 + 1]);
                        }
                    }
                }
            }
            cp_wait<0>();

            __nv_bfloat16* hhN = g_H1h[newp];
            __nv_bfloat16* hlN = g_H1l[newp];
#pragma unroll
            for (int nf = 0; nf < 2; nf++) {
                int jg = j0 + wnB + nf * 8 + colp;
#pragma unroll
                for (int hh = 0; hh < 2; hh++) {
                    int m = m0 + wm + row + hh * 8;
                    const float* gi = g_GI1 + ((size_t)t * B_ + m) * G3_;
                    float2 gr = *(const float2*)(gi + jg);
                    float2 gz = *(const float2*)(gi + 512 + jg);
                    float2 gn = *(const float2*)(gi + 1024 + jg);
                    float r0 = sigm(gr.x + acc[0][nf][hh * 2] + a_br[nf].x);
                    float r1 = sigm(gr.y + acc[0][nf][hh * 2 + 1] + a_br[nf].y);
                    float z0 = sigm(gz.x + acc[1][nf][hh * 2] + a_bz[nf].x);
                    float z1 = sigm(gz.y + acc[1][nf][hh * 2 + 1] + a_bz[nf].y);
                    float n0 = tanhf(gn.x + r0 * (acc[2][nf][hh * 2] + a_bn[nf].x));
                    float n1 = tanhf(gn.y + r1 * (acc[2][nf][hh * 2 + 1] + a_bn[nf].y));
                    float h0 = (1.f - z0) * n0 + z0 * h1p[nf][hh].x;
                    float h1 = (1.f - z1) * n1 + z1 * h1p[nf][hh].y;
                    h1p[nf][hh] = make_float2(h0, h1);
                    __nv_bfloat16 x0, y0, x1, y1;
                    split2(h0, x0, y0); split2(h1, x1, y1);
                    __nv_bfloat162 hv; hv.x = x0; hv.y = x1;
                    __nv_bfloat162 lv; lv.x = y0; lv.y = y1;
                    *(__nv_bfloat162*)(hhN + (size_t)m * H_ + jg) = hv;
                    *(__nv_bfloat162*)(hlN + (size_t)m * H_ + jg) = lv;
                    if (t == L_ - 1)
                        *(float2*)(g_H1fin + (size_t)m * H_ + jg) = make_float2(h0, h1);
                }
            }
        }
        bar_t += 128; gridbar(bar_t);

        // ================= phase B: layer-2 GRU =================
        {
            const __nv_bfloat16* A1h = g_H1h[newp] + (size_t)m0 * H_;
            const __nv_bfloat16* A1l = g_H1l[newp] + (size_t)m0 * H_;
            const __nv_bfloat16* A2h = g_H2h[oldp] + (size_t)m0 * H_;
            const __nv_bfloat16* A2l = g_H2l[oldp] + (size_t)m0 * H_;
            auto stage = [&](int c) {
                const int k0 = c * 32;
                uint32_t d = smb + (uint32_t)(c % 3) * 51200;
                stage_cp(d,         A1h + k0, 64, H_, tid, 256);
                stage_cp(d + 5120,  A1l + k0, 64, H_, tid, 256);
                stage_cp(d + 10240, A2h + k0, 64, H_, tid, 256);
                stage_cp(d + 15360, A2l + k0, 64, H_, tid, 256);
#pragma unroll
                for (int g = 0; g < 3; g++) {
                    const size_t wo = (size_t)(g * 512 + j0) * H_ + k0;
                    stage_cp(d + 20480 + g * 2560, g_W2h + wo, 32, H_, tid, 256);
                    stage_cp(d + 28160 + g * 2560, g_W2l + wo, 32, H_, tid, 256);
                    stage_cp(d + 35840 + g * 2560, g_W3h + wo, 32, H_, tid, 256);
                    stage_cp(d + 43520 + g * 2560, g_W3l + wo, 32, H_, tid, 256);
                }
            };
            stage(0); cp_commit();
            stage(1); cp_commit();

            float aR[2][4], aZ[2][4], aI[2][4], aN[2][4];
#pragma unroll
            for (int nf = 0; nf < 2; nf++)
#pragma unroll
                for (int q = 0; q < 4; q++) {
                    aR[nf][q] = 0.f; aZ[nf][q] = 0.f; aI[nf][q] = 0.f; aN[nf][q] = 0.f;
                }

            for (int c = 0; c < 16; c++) {
                cp_wait<1>();
                __syncthreads();
                if (c + 2 < 16) stage(c + 2);
                cp_commit();
                const uint32_t Ab = smb + (uint32_t)(c % 3) * 51200;
#pragma unroll
                for (int h = 0; h < 2; h++) {
                    const int c0 = h * 16;
                    uint32_t a1H[4], a1L[4], a2H[4], a2L[4];
                    uint32_t ao = ((wm + arow) * 40 + c0 + acol) * 2;
                    ldsm4(a1H, Ab + ao);
                    ldsm4(a1L, Ab + 5120 + ao);
                    ldsm4(a2H, Ab + 10240 + ao);
                    ldsm4(a2L, Ab + 15360 + ao);
                    uint32_t bo = ((wnB + brow) * 40 + c0 + bcol) * 2;
#pragma unroll
                    for (int g = 0; g < 3; g++) {
                        uint32_t w2h[4], w2l[4], w3h[4], w3l[4];
                        ldsm4(w2h, Ab + 20480 + g * 2560 + bo);
                        ldsm4(w2l, Ab + 28160 + g * 2560 + bo);
                        ldsm4(w3h, Ab + 35840 + g * 2560 + bo);
                        ldsm4(w3l, Ab + 43520 + g * 2560 + bo);
                        float (*c1)[4] = (g == 0) ? aR : (g == 1) ? aZ : aI;
                        float (*c2)[4] = (g == 0) ? aR : (g == 1) ? aZ : aN;
#pragma unroll
                        for (int nf = 0; nf < 2; nf++) {
                            mma16816(c1[nf], a1H, w2h[nf * 2], w2h[nf * 2 + 1]);
                            mma16816(c1[nf], a1H, w2l[nf * 2], w2l[nf * 2 + 1]);
                            mma16816(c1[nf], a1L, w2h[nf * 2], w2h[nf * 2 + 1]);
                            mma16816(c2[nf], a2H, w3h[nf * 2], w3h[nf * 2 + 1]);
                            mma16816(c2[nf], a2H, w3l[nf * 2], w3l[nf * 2 + 1]);
                            mma16816(c2[nf], a2L, w3h[nf * 2], w3h[nf * 2 + 1]);
                        }
                    }
                }
            }
            cp_wait<0>();

            float* h2new = g_H2 + (size_t)t * B_ * H_;
            __nv_bfloat16* hhN = g_H2h[newp];
            __nv_bfloat16* hlN = g_H2l[newp];
#pragma unroll
            for (int nf = 0; nf < 2; nf++) {
                int jg = j0 + wnB + nf * 8 + colp;
#pragma unroll
                for (int hh = 0; hh < 2; hh++) {
                    int m = m0 + wm + row + hh * 8;
                    float r0 = sigm(aR[nf][hh * 2] + b_br[nf].x);
                    float r1 = sigm(aR[nf][hh * 2 + 1] + b_br[nf].y);
                    float z0 = sigm(aZ[nf][hh * 2] + b_bz[nf].x);
                    float z1 = sigm(aZ[nf][hh * 2 + 1] + b_bz[nf].y);
                    float n0 = tanhf(aI[nf][hh * 2] + b_bn1[nf].x + r0 * (aN[nf][hh * 2] + b_bn2[nf].x));
                    float n1 = tanhf(aI[nf][hh * 2 + 1] + b_bn1[nf].y + r1 * (aN[nf][hh * 2 + 1] + b_bn2[nf].y));
                    float h0 = (1.f - z0) * n0 + z0 * h2p[nf][hh].x;
                    float h1 = (1.f - z1) * n1 + z1 * h2p[nf][hh].y;
                    h2p[nf][hh] = make_float2(h0, h1);
                    *(float2*)(h2new + (size_t)m * H_ + jg) = make_float2(h0, h1);
                    __nv_bfloat16 x0, y0, x1, y1;
                    split2(h0, x0, y0); split2(h1, x1, y1);
                    __nv_bfloat162 hv; hv.x = x0; hv.y = x1;
                    __nv_bfloat162 lv; lv.x = y0; lv.y = y1;
                    *(__nv_bfloat162*)(hhN + (size_t)m * H_ + jg) = hv;
                    *(__nv_bfloat162*)(hlN + (size_t)m * H_ + jg) = lv;
                }
            }
        }
        bar_t += 128; gridbar(bar_t);
    }
}

// ---------------------------------------------------------------------------
__global__ __launch_bounds__(256) void k_fc(const float* __restrict__ Wfc,
                                            const float* __restrict__ bfc,
                                            float* __restrict__ out) {
    int w = (blockIdx.x * 256 + threadIdx.x) >> 5;
    int lane = threadIdx.x & 31;
    int b = w >> 6, tt = w & 63;
    const float* h = g_H2 + ((size_t)tt * B_ + b) * H_;
    float s = 0.f;
#pragma unroll
    for (int q = 0; q < H_ / 32; q++) s += h[lane + 32 * q] * Wfc[lane + 32 * q];
#pragma unroll
    for (int off = 16; off; off >>= 1) s += __shfl_down_sync(0xffffffffu, s, off);
    if (lane == 0) out[(size_t)b * L_ + tt] = s + bfc[0];
}

__global__ __launch_bounds__(256) void k_copy(float* __restrict__ out) {
    int i = blockIdx.x * 256 + threadIdx.x;
    const int n = B_ * H_;
    if (i < n) {
        out[B_ * L_ + i] = g_H1fin[i];
        out[B_ * L_ + n + i] = g_H2[(size_t)(L_ - 1) * n + i];
    }
}

// ---------------------------------------------------------------------------
extern "C" void kernel_launch(void* const* d_in, const int* in_sizes, int n_in,
                              void* d_out, int out_size) {
    const float* x    = (const float*)d_in[0];
    const float* h1i  = (const float*)d_in[1];
    const float* h2i  = (const float*)d_in[2];
    const float* Wih1 = (const float*)d_in[3];
    const float* Whh1 = (const float*)d_in[4];
    const float* bih1 = (const float*)d_in[5];
    const float* bhh1 = (const float*)d_in[6];
    const float* Wih2 = (const float*)d_in[7];
    const float* Whh2 = (const float*)d_in[8];
    const float* bih2 = (const float*)d_in[9];
    const float* bhh2 = (const float*)d_in[10];
    const float* Wfc  = (const float*)d_in[11];
    const float* bfc  = (const float*)d_in[12];
    float* out = (float*)d_out;

    cudaFuncSetAttribute(k_gi1_tc, cudaFuncAttributeMaxDynamicSharedMemorySize, 153600);
    cudaFuncSetAttribute(k_steps,  cudaFuncAttributeMaxDynamicSharedMemorySize, 153600);

    void* bar_addr = nullptr;
    cudaGetSymbolAddress(&bar_addr, g_bar);
    cudaMemsetAsync(bar_addr, 0, sizeof(unsigned));

    k_prep_w<<<(G3_ * H_ + 255) / 256, 256>>>(Wih1, Whh1, Wih2, Whh2);
    k_prep_h<<<(B_ * H_ + 255) / 256, 256>>>(h1i, h2i);
    k_prep_x<<<(L_ * B_ * H_ + 255) / 256, 256>>>(x);

    k_gi1_tc<<<dim3(8, 4, 64), 512, 153600>>>(bih1);

    k_steps<<<128, 256, 153600>>>(h1i, h2i, bhh1, bih2, bhh2);

    k_fc<<<4096, 256>>>(Wfc, bfc, out);
    k_copy<<<(B_ * H_ + 255) / 256, 256>>>(out);
}

// round 6
// speedup vs baseline: 3.8349x; 1.0007x over previous
#include <cuda_runtime.h>
#include <cuda_bf16.h>
#include <math.h>
#include <stdint.h>

#define B_  512
#define T_  512
#define L_  64
#define H_  512
#define G3_ 1536
#define XW_ 575

// ------------------------- device scratch (no allocs) -----------------------
__device__ __align__(16) float g_GI1[(size_t)L_ * B_ * G3_];  // [t][b][3H]
__device__ __align__(16) float g_H1fin[(size_t)B_ * H_];      // final h1 (t=63)
__device__ __align__(16) float g_H2[(size_t)L_ * B_ * H_];    // fp32 h2 history
__device__ __align__(16) __nv_bfloat16 g_X2[(size_t)L_ * B_ * 1024]; // [t][b][hi|lo]
__device__ __align__(16) __nv_bfloat16 g_W0h[(size_t)G3_ * H_], g_W0l[(size_t)G3_ * H_];
__device__ __align__(16) __nv_bfloat16 g_W1h[(size_t)G3_ * H_], g_W1l[(size_t)G3_ * H_];
__device__ __align__(16) __nv_bfloat16 g_W2h[(size_t)G3_ * H_], g_W2l[(size_t)G3_ * H_];
__device__ __align__(16) __nv_bfloat16 g_W3h[(size_t)G3_ * H_], g_W3l[(size_t)G3_ * H_];
__device__ __align__(16) __nv_bfloat16 g_H1h[2][(size_t)B_ * H_], g_H1l[2][(size_t)B_ * H_];
__device__ __align__(16) __nv_bfloat16 g_H2h[2][(size_t)B_ * H_], g_H2l[2][(size_t)B_ * H_];
// per-m-group barrier counters: [0..255] = barA (grp*32), [256..511] = barB
__device__ unsigned g_bars[512];

__device__ __forceinline__ float sigm(float v) { return 1.f / (1.f + __expf(-v)); }

__device__ __forceinline__ uint32_t smem_u32(const void* p) {
    uint32_t a;
    asm("{ .reg .u64 t; cvta.to.shared.u64 t, %1; cvt.u32.u64 %0, t; }" : "=r"(a) : "l"(p));
    return a;
}
__device__ __forceinline__ void ldsm4(uint32_t* r, uint32_t addr) {
    asm volatile("ldmatrix.sync.aligned.m8n8.x4.shared.b16 {%0,%1,%2,%3}, [%4];"
                 : "=r"(r[0]), "=r"(r[1]), "=r"(r[2]), "=r"(r[3]) : "r"(addr));
}
__device__ __forceinline__ void mma16816(float* c, const uint32_t* a, uint32_t b0, uint32_t b1) {
    asm volatile("mma.sync.aligned.m16n8k16.row.col.f32.bf16.bf16.f32 "
                 "{%0,%1,%2,%3}, {%4,%5,%6,%7}, {%8,%9}, {%0,%1,%2,%3};"
                 : "+f"(c[0]), "+f"(c[1]), "+f"(c[2]), "+f"(c[3])
                 : "r"(a[0]), "r"(a[1]), "r"(a[2]), "r"(a[3]), "r"(b0), "r"(b1));
}
__device__ __forceinline__ void split2(float a, __nv_bfloat16& h, __nv_bfloat16& l) {
    h = __float2bfloat16_rn(a);
    l = __float2bfloat16_rn(a - __bfloat162float(h));
}
__device__ __forceinline__ void cp16(uint32_t dst, const void* src) {
    asm volatile("cp.async.cg.shared.global [%0], [%1], 16;" :: "r"(dst), "l"(src));
}
__device__ __forceinline__ void cp_commit() {
    asm volatile("cp.async.commit_group;" ::: "memory");
}
template <int N> __device__ __forceinline__ void cp_wait() {
    asm volatile("cp.async.wait_group %0;" :: "n"(N) : "memory");
}
__device__ __forceinline__ void stage_cp(uint32_t dst, const __nv_bfloat16* src,
                                         int rows, int stride, int tid, int nthr) {
    for (int i = tid; i < rows * 4; i += nthr) {
        int r = i >> 2, q = i & 3;
        cp16(dst + r * 80 + q * 16, src + (size_t)r * stride + q * 8);
    }
}

// ---------------------------------------------------------------------------
// Prep kernels
// ---------------------------------------------------------------------------
__global__ __launch_bounds__(256) void k_prep_w(const float* __restrict__ W0,
                                                const float* __restrict__ W1,
                                                const float* __restrict__ W2,
                                                const float* __restrict__ W3) {
    size_t i = (size_t)blockIdx.x * 256 + threadIdx.x;
    if (i >= (size_t)G3_ * H_) return;
    __nv_bfloat16 h, l;
    split2(W0[i], h, l); g_W0h[i] = h; g_W0l[i] = l;
    split2(W1[i], h, l); g_W1h[i] = h; g_W1l[i] = l;
    split2(W2[i], h, l); g_W2h[i] = h; g_W2l[i] = l;
    split2(W3[i], h, l); g_W3h[i] = h; g_W3l[i] = l;
}

__global__ __launch_bounds__(256) void k_prep_h(const float* __restrict__ h1i,
                                                const float* __restrict__ h2i) {
    size_t i = (size_t)blockIdx.x * 256 + threadIdx.x;
    if (i >= (size_t)B_ * H_) return;
    __nv_bfloat16 h, l;
    split2(h1i[i], h, l); g_H1h[1][i] = h; g_H1l[1][i] = l;
    split2(h2i[i], h, l); g_H2h[1][i] = h; g_H2l[1][i] = l;
}

__global__ __launch_bounds__(256) void k_prep_x(const float* __restrict__ x) {
    size_t i = (size_t)blockIdx.x * 256 + threadIdx.x;
    if (i >= (size_t)L_ * B_ * H_) return;
    int k = (int)(i % H_);
    int b = (int)((i / H_) % B_);
    int t = (int)(i / ((size_t)B_ * H_));
    __nv_bfloat16 h, l;
    split2(x[(size_t)b * XW_ + t + k], h, l);
    size_t o = ((size_t)t * B_ + b) * 1024;
    g_X2[o + k] = h; g_X2[o + 512 + k] = l;
}

// ---------------------------------------------------------------------------
// k_gi1_tc: GI1[t] = Xwin(t) @ W_ih1^T + b. M=64, N=3x64, K=512 (x3 terms).
// grid (8 j, 8 m, 64 t), 256 thr (8 warps: 2m x 4n), 2 CTAs/SM, 2-stage.
//  chunk: A hi@0 (64x80), A lo@5120, Wh g@10240+g*5120, Wl g@25600+g*5120 = 40960
// ---------------------------------------------------------------------------
__global__ __launch_bounds__(256, 2) void k_gi1_tc(const float* __restrict__ bias) {
    extern __shared__ char sm[];
    const uint32_t smb = smem_u32(sm);
    const int tid = threadIdx.x;
    const int j0 = blockIdx.x * 64;
    const int m0 = blockIdx.y * 64;
    const int t  = blockIdx.z;
    const __nv_bfloat16* A = g_X2 + ((size_t)t * B_ + m0) * 1024;

    auto stage = [&](int c) {
        const int k0 = c * 32;
        uint32_t d = smb + (uint32_t)(c & 1) * 40960;
        stage_cp(d,        A + k0,       64, 1024, tid, 256);
        stage_cp(d + 5120, A + 512 + k0, 64, 1024, tid, 256);
#pragma unroll
        for (int g = 0; g < 3; g++) {
            stage_cp(d + 10240 + g * 5120, g_W0h + (size_t)(g * 512 + j0) * H_ + k0, 64, H_, tid, 256);
            stage_cp(d + 25600 + g * 5120, g_W0l + (size_t)(g * 512 + j0) * H_ + k0, 64, H_, tid, 256);
        }
    };
    stage(0); cp_commit();

    const int wid = tid >> 5, lane = tid & 31;
    const int wm = (wid >> 2) * 32;
    const int wn = (wid & 3) * 16;
    const int arow = lane & 15, acol = (lane >> 4) * 8;
    const int brow = (lane & 7) + ((lane >> 4) << 3), bcol = ((lane >> 3) & 1) * 8;

    float acc[3][2][2][4];
#pragma unroll
    for (int g = 0; g < 3; g++)
#pragma unroll
        for (int mf = 0; mf < 2; mf++)
#pragma unroll
            for (int nf = 0; nf < 2; nf++)
#pragma unroll
                for (int q = 0; q < 4; q++) acc[g][mf][nf][q] = 0.f;

    for (int c = 0; c < 16; c++) {
        cp_wait<0>();
        __syncthreads();
        if (c + 1 < 16) stage(c + 1);
        cp_commit();
        const uint32_t Ab = smb + (uint32_t)(c & 1) * 40960;
#pragma unroll
        for (int h = 0; h < 2; h++) {
            const int c0 = h * 16;
            uint32_t aH[2][4], aL[2][4];
#pragma unroll
            for (int mf = 0; mf < 2; mf++) {
                uint32_t ao = ((wm + mf * 16 + arow) * 40 + c0 + acol) * 2;
                ldsm4(aH[mf], Ab + ao);
                ldsm4(aL[mf], Ab + 5120 + ao);
            }
            uint32_t bo = ((wn + brow) * 40 + c0 + bcol) * 2;
#pragma unroll
            for (int g = 0; g < 3; g++) {
                uint32_t bh[4], bl[4];
                ldsm4(bh, Ab + 10240 + g * 5120 + bo);
                ldsm4(bl, Ab + 25600 + g * 5120 + bo);
#pragma unroll
                for (int mf = 0; mf < 2; mf++)
#pragma unroll
                    for (int nf = 0; nf < 2; nf++) {
                        float* a = acc[g][mf][nf];
                        mma16816(a, aH[mf], bh[nf * 2], bh[nf * 2 + 1]);
                        mma16816(a, aH[mf], bl[nf * 2], bl[nf * 2 + 1]);
                        mma16816(a, aL[mf], bh[nf * 2], bh[nf * 2 + 1]);
                    }
            }
        }
    }

    const int row = lane >> 2, colp = (lane & 3) * 2;
    float* gi = g_GI1 + ((size_t)t * B_ + m0) * G3_;
#pragma unroll
    for (int g = 0; g < 3; g++)
#pragma unroll
        for (int mf = 0; mf < 2; mf++)
#pragma unroll
            for (int nf = 0; nf < 2; nf++) {
                int jg = j0 + wn + nf * 8 + colp;
                float2 bv = *(const float2*)(bias + g * 512 + jg);
#pragma unroll
                for (int hh = 0; hh < 2; hh++) {
                    int m = wm + mf * 16 + row + hh * 8;
                    float2 o;
                    o.x = acc[g][mf][nf][hh * 2 + 0] + bv.x;
                    o.y = acc[g][mf][nf][hh * 2 + 1] + bv.y;
                    *(float2*)(gi + (size_t)m * G3_ + g * 512 + jg) = o;
                }
            }
}

// ---------------------------------------------------------------------------
// k_steps: persistent 2-layer GRU recurrence, 64 steps, 128 CTAs, 256 thr.
// Per-m-group barriers (8 groups x 16 CTAs). Disjoint smem rings:
//   phase A ring: 3 x 25600 @ 0         (A hi@0, lo@5120, W @10240/17920)
//   phase B ring: 3 x 51200 @ 76800     (A1/A2 @0..20479, W @20480..)
// Cross-phase weight prestaging at loop tail; barB wait deferred to next B.
// ---------------------------------------------------------------------------
__global__ __launch_bounds__(256, 1) void k_steps(const float* __restrict__ h1i,
                                                  const float* __restrict__ h2i,
                                                  const float* __restrict__ bhh1,
                                                  const float* __restrict__ bih2,
                                                  const float* __restrict__ bhh2) {
    extern __shared__ char sm[];
    const uint32_t smb = smem_u32(sm);
    const int tid = threadIdx.x;
    const int bid = blockIdx.x;
    const int j0 = (bid & 15) * 32;
    const int m0 = (bid >> 4) * 64;
    const int grp = bid >> 4;
    const int wid = tid >> 5, lane = tid & 31;
    const int wm = (wid >> 1) * 16, wnB = (wid & 1) * 16;
    const int arow = lane & 15, acol = (lane >> 4) * 8;
    const int brow = (lane & 7) + ((lane >> 4) << 3), bcol = ((lane >> 3) & 1) * 8;
    const int row = lane >> 2, colp = (lane & 3) * 2;

    // preload biases + initial hidden state (registers, fixed coords)
    float2 a_br[2], a_bz[2], a_bn[2];
    float2 b_br[2], b_bz[2], b_bn1[2], b_bn2[2];
    float2 h1p[2][2], h2p[2][2];
#pragma unroll
    for (int nf = 0; nf < 2; nf++) {
        int jg = j0 + wnB + nf * 8 + colp;
        a_br[nf] = *(const float2*)(bhh1 + jg);
        a_bz[nf] = *(const float2*)(bhh1 + 512 + jg);
        a_bn[nf] = *(const float2*)(bhh1 + 1024 + jg);
        float2 u, v;
        u = *(const float2*)(bih2 + jg);        v = *(const float2*)(bhh2 + jg);
        b_br[nf] = make_float2(u.x + v.x, u.y + v.y);
        u = *(const float2*)(bih2 + 512 + jg);  v = *(const float2*)(bhh2 + 512 + jg);
        b_bz[nf] = make_float2(u.x + v.x, u.y + v.y);
        b_bn1[nf] = *(const float2*)(bih2 + 1024 + jg);
        b_bn2[nf] = *(const float2*)(bhh2 + 1024 + jg);
#pragma unroll
        for (int hh = 0; hh < 2; hh++) {
            int m = m0 + wm + row + hh * 8;
            h1p[nf][hh] = *(const float2*)(h1i + (size_t)m * H_ + jg);
            h2p[nf][hh] = *(const float2*)(h2i + (size_t)m * H_ + jg);
        }
    }

    // ---- staging helpers ----
    auto stageA_W = [&](int c) {
        const int k0 = c * 32;
        uint32_t d = smb + (uint32_t)(c % 3) * 25600;
#pragma unroll
        for (int g = 0; g < 3; g++) {
            stage_cp(d + 10240 + g * 2560, g_W1h + (size_t)(g * 512 + j0) * H_ + k0, 32, H_, tid, 256);
            stage_cp(d + 17920 + g * 2560, g_W1l + (size_t)(g * 512 + j0) * H_ + k0, 32, H_, tid, 256);
        }
    };
    auto stageA_A = [&](int c, int op) {
        const int k0 = c * 32;
        uint32_t d = smb + (uint32_t)(c % 3) * 25600;
        stage_cp(d,        g_H1h[op] + (size_t)m0 * H_ + k0, 64, H_, tid, 256);
        stage_cp(d + 5120, g_H1l[op] + (size_t)m0 * H_ + k0, 64, H_, tid, 256);
    };
    auto stageB_W = [&](int c) {
        const int k0 = c * 32;
        uint32_t d = smb + 76800u + (uint32_t)(c % 3) * 51200;
#pragma unroll
        for (int g = 0; g < 3; g++) {
            const size_t wo = (size_t)(g * 512 + j0) * H_ + k0;
            stage_cp(d + 20480 + g * 2560, g_W2h + wo, 32, H_, tid, 256);
            stage_cp(d + 28160 + g * 2560, g_W2l + wo, 32, H_, tid, 256);
            stage_cp(d + 35840 + g * 2560, g_W3h + wo, 32, H_, tid, 256);
            stage_cp(d + 43520 + g * 2560, g_W3l + wo, 32, H_, tid, 256);
        }
    };
    auto stageB_A = [&](int c, int op, int np) {
        const int k0 = c * 32;
        uint32_t d = smb + 76800u + (uint32_t)(c % 3) * 51200;
        stage_cp(d,         g_H1h[np] + (size_t)m0 * H_ + k0, 64, H_, tid, 256);
        stage_cp(d + 5120,  g_H1l[np] + (size_t)m0 * H_ + k0, 64, H_, tid, 256);
        stage_cp(d + 10240, g_H2h[op] + (size_t)m0 * H_ + k0, 64, H_, tid, 256);
        stage_cp(d + 15360, g_H2l[op] + (size_t)m0 * H_ + k0, 64, H_, tid, 256);
    };

    // bootstrap: full chunks 0,1 of phase A (t=0, oldp=1)
    stageA_W(0); stageA_A(0, 1); cp_commit();
    stageA_W(1); stageA_A(1, 1); cp_commit();

    unsigned barTA = 0, barTB = 0;
    for (int t = 0; t < L_; t++) {
        const int oldp = (t + 1) & 1, newp = t & 1;

        // prefetch epilogue-A gi values into registers (ready during k-loop)
        float2 gpr[2][2], gpz[2][2], gpn[2][2];
#pragma unroll
        for (int nf = 0; nf < 2; nf++) {
            int jg = j0 + wnB + nf * 8 + colp;
#pragma unroll
            for (int hh = 0; hh < 2; hh++) {
                int m = m0 + wm + row + hh * 8;
                const float* gb = g_GI1 + ((size_t)t * B_ + m) * G3_;
                gpr[nf][hh] = *(const float2*)(gb + jg);
                gpz[nf][hh] = *(const float2*)(gb + 512 + jg);
                gpn[nf][hh] = *(const float2*)(gb + 1024 + jg);
            }
        }

        // ================= phase A: layer-1 GRU =================
        {
            float acc[3][2][4];
#pragma unroll
            for (int g = 0; g < 3; g++)
#pragma unroll
                for (int nf = 0; nf < 2; nf++)
#pragma unroll
                    for (int q = 0; q < 4; q++) acc[g][nf][q] = 0.f;

            for (int c = 0; c < 16; c++) {
                cp_wait<1>();
                __syncthreads();
                if (c < 14) { stageA_W(c + 2); stageA_A(c + 2, oldp); }
                else        { stageB_W(c - 14); }
                cp_commit();
                const uint32_t Ab = smb + (uint32_t)(c % 3) * 25600;
#pragma unroll
                for (int h = 0; h < 2; h++) {
                    const int c0 = h * 16;
                    uint32_t aH[4], aL[4];
                    uint32_t ao = ((wm + arow) * 40 + c0 + acol) * 2;
                    ldsm4(aH, Ab + ao);
                    ldsm4(aL, Ab + 5120 + ao);
                    uint32_t bo = ((wnB + brow) * 40 + c0 + bcol) * 2;
#pragma unroll
                    for (int g = 0; g < 3; g++) {
                        uint32_t bh[4], bl[4];
                        ldsm4(bh, Ab + 10240 + g * 2560 + bo);
                        ldsm4(bl, Ab + 17920 + g * 2560 + bo);
#pragma unroll
                        for (int nf = 0; nf < 2; nf++) {
                            mma16816(acc[g][nf], aH, bh[nf * 2], bh[nf * 2 + 1]);
                            mma16816(acc[g][nf], aH, bl[nf * 2], bl[nf * 2 + 1]);
                            mma16816(acc[g][nf], aL, bh[nf * 2], bh[nf * 2 + 1]);
                        }
                    }
                }
            }

            __nv_bfloat16* hhN = g_H1h[newp];
            __nv_bfloat16* hlN = g_H1l[newp];
#pragma unroll
            for (int nf = 0; nf < 2; nf++) {
                int jg = j0 + wnB + nf * 8 + colp;
#pragma unroll
                for (int hh = 0; hh < 2; hh++) {
                    int m = m0 + wm + row + hh * 8;
                    float r0 = sigm(gpr[nf][hh].x + acc[0][nf][hh * 2] + a_br[nf].x);
                    float r1 = sigm(gpr[nf][hh].y + acc[0][nf][hh * 2 + 1] + a_br[nf].y);
                    float z0 = sigm(gpz[nf][hh].x + acc[1][nf][hh * 2] + a_bz[nf].x);
                    float z1 = sigm(gpz[nf][hh].y + acc[1][nf][hh * 2 + 1] + a_bz[nf].y);
                    float n0 = tanhf(gpn[nf][hh].x + r0 * (acc[2][nf][hh * 2] + a_bn[nf].x));
                    float n1 = tanhf(gpn[nf][hh].y + r1 * (acc[2][nf][hh * 2 + 1] + a_bn[nf].y));
                    float h0 = (1.f - z0) * n0 + z0 * h1p[nf][hh].x;
                    float h1 = (1.f - z1) * n1 + z1 * h1p[nf][hh].y;
                    h1p[nf][hh] = make_float2(h0, h1);
                    __nv_bfloat16 x0, y0, x1, y1;
                    split2(h0, x0, y0); split2(h1, x1, y1);
                    __nv_bfloat162 hv; hv.x = x0; hv.y = x1;
                    __nv_bfloat162 lv; lv.x = y0; lv.y = y1;
                    *(__nv_bfloat162*)(hhN + (size_t)m * H_ + jg) = hv;
                    *(__nv_bfloat162*)(hlN + (size_t)m * H_ + jg) = lv;
                    if (t == L_ - 1)
                        *(float2*)(g_H1fin + (size_t)m * H_ + jg) = make_float2(h0, h1);
                }
            }
        }
        __threadfence();
        __syncthreads();
        if (tid == 0) atomicAdd(&g_bars[grp * 32], 1u);
        barTA += 16;
        // wait: barA(t) (h1 complete) AND barB(t-1) (h2 complete)
        if (tid == 0) {
            while (*(volatile unsigned*)&g_bars[grp * 32] < barTA) { }
            while (*(volatile unsigned*)&g_bars[256 + grp * 32] < barTB) { }
        }
        __syncthreads();
        stageB_A(0, oldp, newp); cp_commit();
        stageB_A(1, oldp, newp); cp_commit();

        // ================= phase B: layer-2 GRU =================
        {
            float aR[2][4], aZ[2][4], aI[2][4], aN[2][4];
#pragma unroll
            for (int nf = 0; nf < 2; nf++)
#pragma unroll
                for (int q = 0; q < 4; q++) {
                    aR[nf][q] = 0.f; aZ[nf][q] = 0.f; aI[nf][q] = 0.f; aN[nf][q] = 0.f;
                }

            for (int c = 0; c < 16; c++) {
                cp_wait<1>();
                __syncthreads();
                if (c < 14) { stageB_W(c + 2); stageB_A(c + 2, oldp, newp); }
                else        { stageA_W(c - 14); }
                cp_commit();
                const uint32_t Ab = smb + 76800u + (uint32_t)(c % 3) * 51200;
#pragma unroll
                for (int h = 0; h < 2; h++) {
                    const int c0 = h * 16;
                    uint32_t a1H[4], a1L[4], a2H[4], a2L[4];
                    uint32_t ao = ((wm + arow) * 40 + c0 + acol) * 2;
                    ldsm4(a1H, Ab + ao);
                    ldsm4(a1L, Ab + 5120 + ao);
                    ldsm4(a2H, Ab + 10240 + ao);
                    ldsm4(a2L, Ab + 15360 + ao);
                    uint32_t bo = ((wnB + brow) * 40 + c0 + bcol) * 2;
#pragma unroll
                    for (int g = 0; g < 3; g++) {
                        uint32_t w2h[4], w2l[4], w3h[4], w3l[4];
                        ldsm4(w2h, Ab + 20480 + g * 2560 + bo);
                        ldsm4(w2l, Ab + 28160 + g * 2560 + bo);
                        ldsm4(w3h, Ab + 35840 + g * 2560 + bo);
                        ldsm4(w3l, Ab + 43520 + g * 2560 + bo);
                        float (*c1)[4] = (g == 0) ? aR : (g == 1) ? aZ : aI;
                        float (*c2)[4] = (g == 0) ? aR : (g == 1) ? aZ : aN;
#pragma unroll
                        for (int nf = 0; nf < 2; nf++) {
                            mma16816(c1[nf], a1H, w2h[nf * 2], w2h[nf * 2 + 1]);
                            mma16816(c1[nf], a1H, w2l[nf * 2], w2l[nf * 2 + 1]);
                            mma16816(c1[nf], a1L, w2h[nf * 2], w2h[nf * 2 + 1]);
                            mma16816(c2[nf], a2H, w3h[nf * 2], w3h[nf * 2 + 1]);
                            mma16816(c2[nf], a2H, w3l[nf * 2], w3l[nf * 2 + 1]);
                            mma16816(c2[nf], a2L, w3h[nf * 2], w3h[nf * 2 + 1]);
                        }
                    }
                }
            }

            float* h2new = g_H2 + (size_t)t * B_ * H_;
            __nv_bfloat16* hhN = g_H2h[newp];
            __nv_bfloat16* hlN = g_H2l[newp];
#pragma unroll
            for (int nf = 0; nf < 2; nf++) {
                int jg = j0 + wnB + nf * 8 + colp;
#pragma unroll
                for (int hh = 0; hh < 2; hh++) {
                    int m = m0 + wm + row + hh * 8;
                    float r0 = sigm(aR[nf][hh * 2] + b_br[nf].x);
                    float r1 = sigm(aR[nf][hh * 2 + 1] + b_br[nf].y);
                    float z0 = sigm(aZ[nf][hh * 2] + b_bz[nf].x);
                    float z1 = sigm(aZ[nf][hh * 2 + 1] + b_bz[nf].y);
                    float n0 = tanhf(aI[nf][hh * 2] + b_bn1[nf].x + r0 * (aN[nf][hh * 2] + b_bn2[nf].x));
                    float n1 = tanhf(aI[nf][hh * 2 + 1] + b_bn1[nf].y + r1 * (aN[nf][hh * 2 + 1] + b_bn2[nf].y));
                    float h0 = (1.f - z0) * n0 + z0 * h2p[nf][hh].x;
                    float h1 = (1.f - z1) * n1 + z1 * h2p[nf][hh].y;
                    h2p[nf][hh] = make_float2(h0, h1);
                    *(float2*)(h2new + (size_t)m * H_ + jg) = make_float2(h0, h1);
                    __nv_bfloat16 x0, y0, x1, y1;
                    split2(h0, x0, y0); split2(h1, x1, y1);
                    __nv_bfloat162 hv; hv.x = x0; hv.y = x1;
                    __nv_bfloat162 lv; lv.x = y0; lv.y = y1;
                    *(__nv_bfloat162*)(hhN + (size_t)m * H_ + jg) = hv;
                    *(__nv_bfloat162*)(hlN + (size_t)m * H_ + jg) = lv;
                }
            }
        }
        __threadfence();
        __syncthreads();
        if (tid == 0) atomicAdd(&g_bars[256 + grp * 32], 1u);
        barTB += 16;
        // prestage next step's phase-A A-operand (h1[t] — barA(t) already waited)
        if (t + 1 < L_) {
            stageA_A(0, newp); cp_commit();
            stageA_A(1, newp); cp_commit();
        }
    }
    cp_wait<0>();
}

// ---------------------------------------------------------------------------
__global__ __launch_bounds__(256) void k_fc(const float* __restrict__ Wfc,
                                            const float* __restrict__ bfc,
                                            float* __restrict__ out) {
    int w = (blockIdx.x * 256 + threadIdx.x) >> 5;
    int lane = threadIdx.x & 31;
    int b = w >> 6, tt = w & 63;
    const float* h = g_H2 + ((size_t)tt * B_ + b) * H_;
    float s = 0.f;
#pragma unroll
    for (int q = 0; q < H_ / 32; q++) s += h[lane + 32 * q] * Wfc[lane + 32 * q];
#pragma unroll
    for (int off = 16; off; off >>= 1) s += __shfl_down_sync(0xffffffffu, s, off);
    if (lane == 0) out[(size_t)b * L_ + tt] = s + bfc[0];
}

__global__ __launch_bounds__(256) void k_copy(float* __restrict__ out) {
    int i = blockIdx.x * 256 + threadIdx.x;
    const int n = B_ * H_;
    if (i < n) {
        out[B_ * L_ + i] = g_H1fin[i];
        out[B_ * L_ + n + i] = g_H2[(size_t)(L_ - 1) * n + i];
    }
}

// ---------------------------------------------------------------------------
extern "C" void kernel_launch(void* const* d_in, const int* in_sizes, int n_in,
                              void* d_out, int out_size) {
    const float* x    = (const float*)d_in[0];
    const float* h1i  = (const float*)d_in[1];
    const float* h2i  = (const float*)d_in[2];
    const float* Wih1 = (const float*)d_in[3];
    const float* Whh1 = (const float*)d_in[4];
    const float* bih1 = (const float*)d_in[5];
    const float* bhh1 = (const float*)d_in[6];
    const float* Wih2 = (const float*)d_in[7];
    const float* Whh2 = (const float*)d_in[8];
    const float* bih2 = (const float*)d_in[9];
    const float* bhh2 = (const float*)d_in[10];
    const float* Wfc  = (const float*)d_in[11];
    const float* bfc  = (const float*)d_in[12];
    float* out = (float*)d_out;

    cudaFuncSetAttribute(k_gi1_tc, cudaFuncAttributeMaxDynamicSharedMemorySize, 81920);
    cudaFuncSetAttribute(k_steps,  cudaFuncAttributeMaxDynamicSharedMemorySize, 230400);

    void* bar_addr = nullptr;
    cudaGetSymbolAddress(&bar_addr, g_bars);
    cudaMemsetAsync(bar_addr, 0, 512 * sizeof(unsigned));

    k_prep_w<<<(G3_ * H_ + 255) / 256, 256>>>(Wih1, Whh1, Wih2, Whh2);
    k_prep_h<<<(B_ * H_ + 255) / 256, 256>>>(h1i, h2i);
    k_prep_x<<<(L_ * B_ * H_ + 255) / 256, 256>>>(x);

    k_gi1_tc<<<dim3(8, 8, 64), 256, 81920>>>(bih1);

    k_steps<<<128, 256, 230400>>>(h1i, h2i, bhh1, bih2, bhh2);

    k_fc<<<4096, 256>>>(Wfc, bfc, out);
    k_copy<<<(B_ * H_ + 255) / 256, 256>>>(out);
}

// round 8
// speedup vs baseline: 4.0277x; 1.0503x over previous
#include <cuda_runtime.h>
#include <cuda_bf16.h>
#include <math.h>
#include <stdint.h>

#define B_  512
#define T_  512
#define L_  64
#define H_  512
#define G3_ 1536
#define XW_ 575

// ------------------------- device scratch (no allocs) -----------------------
__device__ __align__(16) float g_GI1[(size_t)L_ * B_ * G3_];  // [t][b][3H]
__device__ __align__(16) float g_H1fin[(size_t)B_ * H_];      // final h1 (t=63)
__device__ __align__(16) float g_H2[(size_t)L_ * B_ * H_];    // fp32 h2 history
__device__ __align__(16) __nv_bfloat16 g_X2[(size_t)L_ * B_ * 1024]; // [t][b][hi|lo]
__device__ __align__(16) __nv_bfloat16 g_W0h[(size_t)G3_ * H_], g_W0l[(size_t)G3_ * H_];
__device__ __align__(16) __nv_bfloat16 g_W1h[(size_t)G3_ * H_], g_W1l[(size_t)G3_ * H_];
__device__ __align__(16) __nv_bfloat16 g_W2h[(size_t)G3_ * H_], g_W2l[(size_t)G3_ * H_];
__device__ __align__(16) __nv_bfloat16 g_W3h[(size_t)G3_ * H_], g_W3l[(size_t)G3_ * H_];
__device__ __align__(16) __nv_bfloat16 g_H1h[2][(size_t)B_ * H_], g_H1l[2][(size_t)B_ * H_];
__device__ __align__(16) __nv_bfloat16 g_H2h[2][(size_t)B_ * H_], g_H2l[2][(size_t)B_ * H_];
__device__ unsigned g_bars[512];   // per-m-group barrier counters (stride 32)

__device__ __forceinline__ float sigm(float v) { return 1.f / (1.f + __expf(-v)); }

__device__ __forceinline__ uint32_t smem_u32(const void* p) {
    uint32_t a;
    asm("{ .reg .u64 t; cvta.to.shared.u64 t, %1; cvt.u32.u64 %0, t; }" : "=r"(a) : "l"(p));
    return a;
}
__device__ __forceinline__ void ldsm4(uint32_t* r, uint32_t addr) {
    asm volatile("ldmatrix.sync.aligned.m8n8.x4.shared.b16 {%0,%1,%2,%3}, [%4];"
                 : "=r"(r[0]), "=r"(r[1]), "=r"(r[2]), "=r"(r[3]) : "r"(addr));
}
__device__ __forceinline__ void ldsm2(uint32_t* r, uint32_t addr) {
    asm volatile("ldmatrix.sync.aligned.m8n8.x2.shared.b16 {%0,%1}, [%2];"
                 : "=r"(r[0]), "=r"(r[1]) : "r"(addr));
}
__device__ __forceinline__ void mma16816(float* c, const uint32_t* a, uint32_t b0, uint32_t b1) {
    asm volatile("mma.sync.aligned.m16n8k16.row.col.f32.bf16.bf16.f32 "
                 "{%0,%1,%2,%3}, {%4,%5,%6,%7}, {%8,%9}, {%0,%1,%2,%3};"
                 : "+f"(c[0]), "+f"(c[1]), "+f"(c[2]), "+f"(c[3])
                 : "r"(a[0]), "r"(a[1]), "r"(a[2]), "r"(a[3]), "r"(b0), "r"(b1));
}
__device__ __forceinline__ void split2(float a, __nv_bfloat16& h, __nv_bfloat16& l) {
    h = __float2bfloat16_rn(a);
    l = __float2bfloat16_rn(a - __bfloat162float(h));
}
__device__ __forceinline__ void cp16(uint32_t dst, const void* src) {
    asm volatile("cp.async.cg.shared.global [%0], [%1], 16;" :: "r"(dst), "l"(src));
}
__device__ __forceinline__ void cp_commit() {
    asm volatile("cp.async.commit_group;" ::: "memory");
}
template <int N> __device__ __forceinline__ void cp_wait() {
    asm volatile("cp.async.wait_group %0;" :: "n"(N) : "memory");
}
__device__ __forceinline__ void stage_cp(uint32_t dst, const __nv_bfloat16* src,
                                         int rows, int stride, int tid, int nthr) {
    for (int i = tid; i < rows * 4; i += nthr) {
        int r = i >> 2, q = i & 3;
        cp16(dst + r * 80 + q * 16, src + (size_t)r * stride + q * 8);
    }
}

// ---------------------------------------------------------------------------
// Prep kernels
// ---------------------------------------------------------------------------
__global__ __launch_bounds__(256) void k_prep_w(const float* __restrict__ W0,
                                                const float* __restrict__ W1,
                                                const float* __restrict__ W2,
                                                const float* __restrict__ W3) {
    size_t i = (size_t)blockIdx.x * 256 + threadIdx.x;
    if (i >= (size_t)G3_ * H_) return;
    __nv_bfloat16 h, l;
    split2(W0[i], h, l); g_W0h[i] = h; g_W0l[i] = l;
    split2(W1[i], h, l); g_W1h[i] = h; g_W1l[i] = l;
    split2(W2[i], h, l); g_W2h[i] = h; g_W2l[i] = l;
    split2(W3[i], h, l); g_W3h[i] = h; g_W3l[i] = l;
}

__global__ __launch_bounds__(256) void k_prep_h(const float* __restrict__ h1i,
                                                const float* __restrict__ h2i) {
    size_t i = (size_t)blockIdx.x * 256 + threadIdx.x;
    if (i >= (size_t)B_ * H_) return;
    __nv_bfloat16 h, l;
    split2(h1i[i], h, l); g_H1h[1][i] = h; g_H1l[1][i] = l;
    split2(h2i[i], h, l); g_H2h[1][i] = h; g_H2l[1][i] = l;
}

__global__ __launch_bounds__(256) void k_prep_x(const float* __restrict__ x) {
    size_t i = (size_t)blockIdx.x * 256 + threadIdx.x;
    if (i >= (size_t)L_ * B_ * H_) return;
    int k = (int)(i % H_);
    int b = (int)((i / H_) % B_);
    int t = (int)(i / ((size_t)B_ * H_));
    __nv_bfloat16 h, l;
    split2(x[(size_t)b * XW_ + t + k], h, l);
    size_t o = ((size_t)t * B_ + b) * 1024;
    g_X2[o + k] = h; g_X2[o + 512 + k] = l;
}

// ---------------------------------------------------------------------------
// k_gi1_tc: unchanged from round 5 (M=64, N=3x64, 2 CTAs/SM, 2-stage)
// ---------------------------------------------------------------------------
__global__ __launch_bounds__(256, 2) void k_gi1_tc(const float* __restrict__ bias) {
    extern __shared__ char sm[];
    const uint32_t smb = smem_u32(sm);
    const int tid = threadIdx.x;
    const int j0 = blockIdx.x * 64;
    const int m0 = blockIdx.y * 64;
    const int t  = blockIdx.z;
    const __nv_bfloat16* A = g_X2 + ((size_t)t * B_ + m0) * 1024;

    auto stage = [&](int c) {
        const int k0 = c * 32;
        uint32_t d = smb + (uint32_t)(c & 1) * 40960;
        stage_cp(d,        A + k0,       64, 1024, tid, 256);
        stage_cp(d + 5120, A + 512 + k0, 64, 1024, tid, 256);
#pragma unroll
        for (int g = 0; g < 3; g++) {
            stage_cp(d + 10240 + g * 5120, g_W0h + (size_t)(g * 512 + j0) * H_ + k0, 64, H_, tid, 256);
            stage_cp(d + 25600 + g * 5120, g_W0l + (size_t)(g * 512 + j0) * H_ + k0, 64, H_, tid, 256);
        }
    };
    stage(0); cp_commit();

    const int wid = tid >> 5, lane = tid & 31;
    const int wm = (wid >> 2) * 32;
    const int wn = (wid & 3) * 16;
    const int arow = lane & 15, acol = (lane >> 4) * 8;
    const int brow = (lane & 7) + ((lane >> 4) << 3), bcol = ((lane >> 3) & 1) * 8;

    float acc[3][2][2][4];
#pragma unroll
    for (int g = 0; g < 3; g++)
#pragma unroll
        for (int mf = 0; mf < 2; mf++)
#pragma unroll
            for (int nf = 0; nf < 2; nf++)
#pragma unroll
                for (int q = 0; q < 4; q++) acc[g][mf][nf][q] = 0.f;

    for (int c = 0; c < 16; c++) {
        cp_wait<0>();
        __syncthreads();
        if (c + 1 < 16) stage(c + 1);
        cp_commit();
        const uint32_t Ab = smb + (uint32_t)(c & 1) * 40960;
#pragma unroll
        for (int h = 0; h < 2; h++) {
            const int c0 = h * 16;
            uint32_t aH[2][4], aL[2][4];
#pragma unroll
            for (int mf = 0; mf < 2; mf++) {
                uint32_t ao = ((wm + mf * 16 + arow) * 40 + c0 + acol) * 2;
                ldsm4(aH[mf], Ab + ao);
                ldsm4(aL[mf], Ab + 5120 + ao);
            }
            uint32_t bo = ((wn + brow) * 40 + c0 + bcol) * 2;
#pragma unroll
            for (int g = 0; g < 3; g++) {
                uint32_t bh[4], bl[4];
                ldsm4(bh, Ab + 10240 + g * 5120 + bo);
                ldsm4(bl, Ab + 25600 + g * 5120 + bo);
#pragma unroll
                for (int mf = 0; mf < 2; mf++)
#pragma unroll
                    for (int nf = 0; nf < 2; nf++) {
                        float* a = acc[g][mf][nf];
                        mma16816(a, aH[mf], bh[nf * 2], bh[nf * 2 + 1]);
                        mma16816(a, aH[mf], bl[nf * 2], bl[nf * 2 + 1]);
                        mma16816(a, aL[mf], bh[nf * 2], bh[nf * 2 + 1]);
                    }
            }
        }
    }

    const int row = lane >> 2, colp = (lane & 3) * 2;
    float* gi = g_GI1 + ((size_t)t * B_ + m0) * G3_;
#pragma unroll
    for (int g = 0; g < 3; g++)
#pragma unroll
        for (int mf = 0; mf < 2; mf++)
#pragma unroll
            for (int nf = 0; nf < 2; nf++) {
                int jg = j0 + wn + nf * 8 + colp;
                float2 bv = *(const float2*)(bias + g * 512 + jg);
#pragma unroll
                for (int hh = 0; hh < 2; hh++) {
                    int m = wm + mf * 16 + row + hh * 8;
                    float2 o;
                    o.x = acc[g][mf][nf][hh * 2 + 0] + bv.x;
                    o.y = acc[g][mf][nf][hh * 2 + 1] + bv.y;
                    *(float2*)(gi + (size_t)m * G3_ + g * 512 + jg) = o;
                }
            }
}

// ---------------------------------------------------------------------------
// k_steps: persistent merged recurrence. 65 iterations; iteration i computes
//   h1(i) = GRU1(gi1(i), h1(i-1))            [skip i==64]
//   h2(i-1) = GRU2(h1(i-1), h2(i-2))         [skip i==0]
// ONE per-m-group barrier per iteration. 128 CTAs (16 j x 8 m), 256 thr,
// warp tile m32 x n8/gate (8 warps = 2m x 4n). B frags via ldmatrix.x2.
// Pass 1 (chunks 0-15): A = h1old hi/lo; W1 (->L1 acc) + W2 (->L2 acc) fused.
// Pass 2 (chunks 16-31): A = h2old hi/lo; W3 (->L2 acc).
// Ring: 4 slots x 40960 B; slot layout:
//   A hi@0 (64x80), A lo@5120, W1h g@10240+2560g, W1l@17920+, W2h@25600+, W2l@33280+
//   (pass 2 uses only first 25600: A + W3h@10240 + W3l@17920)
// ---------------------------------------------------------------------------
__global__ __launch_bounds__(256, 1) void k_steps(const float* __restrict__ h1i,
                                                  const float* __restrict__ h2i,
                                                  const float* __restrict__ bhh1,
                                                  const float* __restrict__ bih2,
                                                  const float* __restrict__ bhh2) {
    extern __shared__ char sm[];
    const uint32_t smb = smem_u32(sm);
    const int tid = threadIdx.x;
    const int bid = blockIdx.x;
    const int j0 = (bid & 15) * 32;
    const int m0 = (bid >> 4) * 64;
    const int grp = bid >> 4;
    const int wid = tid >> 5, lane = tid & 31;
    const int wm = (wid & 1) * 32;        // warp m offset (2 groups of 32)
    const int wn8 = (wid >> 1) * 8;       // warp n offset within 32-col gate tile
    const int arow = lane & 15, acol = (lane >> 4) * 8;
    const int brow2 = lane & 7, bcol2 = ((lane >> 3) & 1) * 8;
    const int row = lane >> 2, colp = (lane & 3) * 2;
    const int jg = j0 + wn8 + colp;       // this thread's 2 output cols (jg, jg+1)

    // biases (this thread's 2 cols)
    const float2 a_br = *(const float2*)(bhh1 + jg);
    const float2 a_bz = *(const float2*)(bhh1 + 512 + jg);
    const float2 a_bn = *(const float2*)(bhh1 + 1024 + jg);
    float2 u, v;
    u = *(const float2*)(bih2 + jg);       v = *(const float2*)(bhh2 + jg);
    const float2 b_br = make_float2(u.x + v.x, u.y + v.y);
    u = *(const float2*)(bih2 + 512 + jg); v = *(const float2*)(bhh2 + 512 + jg);
    const float2 b_bz = make_float2(u.x + v.x, u.y + v.y);
    const float2 b_bn1 = *(const float2*)(bih2 + 1024 + jg);
    const float2 b_bn2 = *(const float2*)(bhh2 + 1024 + jg);

    // carried hidden state at this thread's output coords
    float2 h1p[2][2], h2p[2][2];
#pragma unroll
    for (int mf = 0; mf < 2; mf++)
#pragma unroll
        for (int hh = 0; hh < 2; hh++) {
            int m = m0 + wm + mf * 16 + row + hh * 8;
            h1p[mf][hh] = *(const float2*)(h1i + (size_t)m * H_ + jg);
            h2p[mf][hh] = *(const float2*)(h2i + (size_t)m * H_ + jg);
        }

    unsigned barT = 0;
    for (int i = 0; i <= L_; i++) {
        const int op1 = (i + 1) & 1;   // h1(i-1) buffer
        const int op2 = i & 1;         // h2(i-2) buffer

        auto stageg = [&](int gc) {
            uint32_t d = smb + (uint32_t)(gc & 3) * 40960u;
            if (gc < 16) {
                const int k0 = gc * 32;
                stage_cp(d,        g_H1h[op1] + (size_t)m0 * H_ + k0, 64, H_, tid, 256);
                stage_cp(d + 5120, g_H1l[op1] + (size_t)m0 * H_ + k0, 64, H_, tid, 256);
#pragma unroll
                for (int g = 0; g < 3; g++) {
                    const size_t wo = (size_t)(g * 512 + j0) * H_ + k0;
                    stage_cp(d + 10240 + g * 2560, g_W1h + wo, 32, H_, tid, 256);
                    stage_cp(d + 17920 + g * 2560, g_W1l + wo, 32, H_, tid, 256);
                    stage_cp(d + 25600 + g * 2560, g_W2h + wo, 32, H_, tid, 256);
                    stage_cp(d + 33280 + g * 2560, g_W2l + wo, 32, H_, tid, 256);
                }
            } else {
                const int k0 = (gc - 16) * 32;
                stage_cp(d,        g_H2h[op2] + (size_t)m0 * H_ + k0, 64, H_, tid, 256);
                stage_cp(d + 5120, g_H2l[op2] + (size_t)m0 * H_ + k0, 64, H_, tid, 256);
#pragma unroll
                for (int g = 0; g < 3; g++) {
                    const size_t wo = (size_t)(g * 512 + j0) * H_ + k0;
                    stage_cp(d + 10240 + g * 2560, g_W3h + wo, 32, H_, tid, 256);
                    stage_cp(d + 17920 + g * 2560, g_W3l + wo, 32, H_, tid, 256);
                }
            }
        };

        stageg(0); cp_commit();
        stageg(1); cp_commit();
        stageg(2); cp_commit();

        float accL[3][2][4];                      // L1: r,z,n
        float aR[2][4], aZ[2][4], aI[2][4], aN[2][4];  // L2
#pragma unroll
        for (int g = 0; g < 3; g++)
#pragma unroll
            for (int mf = 0; mf < 2; mf++)
#pragma unroll
                for (int q = 0; q < 4; q++) accL[g][mf][q] = 0.f;
#pragma unroll
        for (int mf = 0; mf < 2; mf++)
#pragma unroll
            for (int q = 0; q < 4; q++) {
                aR[mf][q] = 0.f; aZ[mf][q] = 0.f; aI[mf][q] = 0.f; aN[mf][q] = 0.f;
            }

        for (int gc = 0; gc < 32; gc++) {
            cp_wait<2>();
            __syncthreads();
            if (gc + 3 < 32) stageg(gc + 3);
            cp_commit();
            const uint32_t Ab = smb + (uint32_t)(gc & 3) * 40960u;
            if (gc < 16) {
#pragma unroll
                for (int h = 0; h < 2; h++) {
                    const int c0 = h * 16;
                    uint32_t aH[2][4], aL[2][4];
#pragma unroll
                    for (int mf = 0; mf < 2; mf++) {
                        uint32_t ao = ((wm + mf * 16 + arow) * 40 + c0 + acol) * 2;
                        ldsm4(aH[mf], Ab + ao);
                        ldsm4(aL[mf], Ab + 5120 + ao);
                    }
                    const uint32_t bo = ((wn8 + brow2) * 40 + c0 + bcol2) * 2;
#pragma unroll
                    for (int g = 0; g < 3; g++) {
                        uint32_t b1h[2], b1l[2], b2h[2], b2l[2];
                        ldsm2(b1h, Ab + 10240 + g * 2560 + bo);
                        ldsm2(b1l, Ab + 17920 + g * 2560 + bo);
                        ldsm2(b2h, Ab + 25600 + g * 2560 + bo);
                        ldsm2(b2l, Ab + 33280 + g * 2560 + bo);
#pragma unroll
                        for (int mf = 0; mf < 2; mf++) {
                            mma16816(accL[g][mf], aH[mf], b1h[0], b1h[1]);
                            mma16816(accL[g][mf], aH[mf], b1l[0], b1l[1]);
                            mma16816(accL[g][mf], aL[mf], b1h[0], b1h[1]);
                            float* c2 = (g == 0) ? aR[mf] : (g == 1) ? aZ[mf] : aI[mf];
                            mma16816(c2, aH[mf], b2h[0], b2h[1]);
                            mma16816(c2, aH[mf], b2l[0], b2l[1]);
                            mma16816(c2, aL[mf], b2h[0], b2h[1]);
                        }
                    }
                }
            } else {
#pragma unroll
                for (int h = 0; h < 2; h++) {
                    const int c0 = h * 16;
                    uint32_t aH[2][4], aL[2][4];
#pragma unroll
                    for (int mf = 0; mf < 2; mf++) {
                        uint32_t ao = ((wm + mf * 16 + arow) * 40 + c0 + acol) * 2;
                        ldsm4(aH[mf], Ab + ao);
                        ldsm4(aL[mf], Ab + 5120 + ao);
                    }
                    const uint32_t bo = ((wn8 + brow2) * 40 + c0 + bcol2) * 2;
#pragma unroll
                    for (int g = 0; g < 3; g++) {
                        uint32_t b3h[2], b3l[2];
                        ldsm2(b3h, Ab + 10240 + g * 2560 + bo);
                        ldsm2(b3l, Ab + 17920 + g * 2560 + bo);
#pragma unroll
                        for (int mf = 0; mf < 2; mf++) {
                            float* c2 = (g == 0) ? aR[mf] : (g == 1) ? aZ[mf] : aN[mf];
                            mma16816(c2, aH[mf], b3h[0], b3h[1]);
                            mma16816(c2, aH[mf], b3l[0], b3l[1]);
                            mma16816(c2, aL[mf], b3h[0], b3h[1]);
                        }
                    }
                }
            }
        }

        // ---------------- L1 epilogue: h1(i) ----------------
        if (i < L_) {
            __nv_bfloat16* hhN = g_H1h[i & 1];
            __nv_bfloat16* hlN = g_H1l[i & 1];
#pragma unroll
            for (int mf = 0; mf < 2; mf++)
#pragma unroll
                for (int hh = 0; hh < 2; hh++) {
                    int m = m0 + wm + mf * 16 + row + hh * 8;
                    const float* gb = g_GI1 + ((size_t)i * B_ + m) * G3_;
                    float2 gr = *(const float2*)(gb + jg);
                    float2 gz = *(const float2*)(gb + 512 + jg);
                    float2 gn = *(const float2*)(gb + 1024 + jg);
                    float r0 = sigm(gr.x + accL[0][mf][hh * 2] + a_br.x);
                    float r1 = sigm(gr.y + accL[0][mf][hh * 2 + 1] + a_br.y);
                    float z0 = sigm(gz.x + accL[1][mf][hh * 2] + a_bz.x);
                    float z1 = sigm(gz.y + accL[1][mf][hh * 2 + 1] + a_bz.y);
                    float n0 = tanhf(gn.x + r0 * (accL[2][mf][hh * 2] + a_bn.x));
                    float n1 = tanhf(gn.y + r1 * (accL[2][mf][hh * 2 + 1] + a_bn.y));
                    float h0 = (1.f - z0) * n0 + z0 * h1p[mf][hh].x;
                    float h1 = (1.f - z1) * n1 + z1 * h1p[mf][hh].y;
                    h1p[mf][hh] = make_float2(h0, h1);
                    __nv_bfloat16 x0, y0, x1, y1;
                    split2(h0, x0, y0); split2(h1, x1, y1);
                    __nv_bfloat162 hv; hv.x = x0; hv.y = x1;
                    __nv_bfloat162 lv; lv.x = y0; lv.y = y1;
                    *(__nv_bfloat162*)(hhN + (size_t)m * H_ + jg) = hv;
                    *(__nv_bfloat162*)(hlN + (size_t)m * H_ + jg) = lv;
                    if (i == L_ - 1)
                        *(float2*)(g_H1fin + (size_t)m * H_ + jg) = make_float2(h0, h1);
                }
        }

        // ---------------- L2 epilogue: h2(i-1) ----------------
        if (i > 0) {
            const int t2 = i - 1;
            float* h2new = g_H2 + (size_t)t2 * B_ * H_;
            __nv_bfloat16* hhN = g_H2h[t2 & 1];
            __nv_bfloat16* hlN = g_H2l[t2 & 1];
#pragma unroll
            for (int mf = 0; mf < 2; mf++)
#pragma unroll
                for (int hh = 0; hh < 2; hh++) {
                    int m = m0 + wm + mf * 16 + row + hh * 8;
                    float r0 = sigm(aR[mf][hh * 2] + b_br.x);
                    float r1 = sigm(aR[mf][hh * 2 + 1] + b_br.y);
                    float z0 = sigm(aZ[mf][hh * 2] + b_bz.x);
                    float z1 = sigm(aZ[mf][hh * 2 + 1] + b_bz.y);
                    float n0 = tanhf(aI[mf][hh * 2] + b_bn1.x + r0 * (aN[mf][hh * 2] + b_bn2.x));
                    float n1 = tanhf(aI[mf][hh * 2 + 1] + b_bn1.y + r1 * (aN[mf][hh * 2 + 1] + b_bn2.y));
                    float h0 = (1.f - z0) * n0 + z0 * h2p[mf][hh].x;
                    float h1 = (1.f - z1) * n1 + z1 * h2p[mf][hh].y;
                    h2p[mf][hh] = make_float2(h0, h1);
                    *(float2*)(h2new + (size_t)m * H_ + jg) = make_float2(h0, h1);
                    __nv_bfloat16 x0, y0, x1, y1;
                    split2(h0, x0, y0); split2(h1, x1, y1);
                    __nv_bfloat162 hv; hv.x = x0; hv.y = x1;
                    __nv_bfloat162 lv; lv.x = y0; lv.y = y1;
                    *(__nv_bfloat162*)(hhN + (size_t)m * H_ + jg) = hv;
                    *(__nv_bfloat162*)(hlN + (size_t)m * H_ + jg) = lv;
                }
        }

        // ---------------- per-m-group barrier ----------------
        __threadfence();
        __syncthreads();
        if (tid == 0) atomicAdd(&g_bars[grp * 32], 1u);
        barT += 16;
        if (tid == 0) {
            while (*(volatile unsigned*)&g_bars[grp * 32] < barT) { }
        }
        __syncthreads();
    }
}

// ---------------------------------------------------------------------------
__global__ __launch_bounds__(256) void k_fc(const float* __restrict__ Wfc,
                                            const float* __restrict__ bfc,
                                            float* __restrict__ out) {
    int w = (blockIdx.x * 256 + threadIdx.x) >> 5;
    int lane = threadIdx.x & 31;
    int b = w >> 6, tt = w & 63;
    const float* h = g_H2 + ((size_t)tt * B_ + b) * H_;
    float s = 0.f;
#pragma unroll
    for (int q = 0; q < H_ / 32; q++) s += h[lane + 32 * q] * Wfc[lane + 32 * q];
#pragma unroll
    for (int off = 16; off; off >>= 1) s += __shfl_down_sync(0xffffffffu, s, off);
    if (lane == 0) out[(size_t)b * L_ + tt] = s + bfc[0];
}

__global__ __launch_bounds__(256) void k_copy(float* __restrict__ out) {
    int i = blockIdx.x * 256 + threadIdx.x;
    const int n = B_ * H_;
    if (i < n) {
        out[B_ * L_ + i] = g_H1fin[i];
        out[B_ * L_ + n + i] = g_H2[(size_t)(L_ - 1) * n + i];
    }
}

// ---------------------------------------------------------------------------
extern "C" void kernel_launch(void* const* d_in, const int* in_sizes, int n_in,
                              void* d_out, int out_size) {
    const float* x    = (const float*)d_in[0];
    const float* h1i  = (const float*)d_in[1];
    const float* h2i  = (const float*)d_in[2];
    const float* Wih1 = (const float*)d_in[3];
    const float* Whh1 = (const float*)d_in[4];
    const float* bih1 = (const float*)d_in[5];
    const float* bhh1 = (const float*)d_in[6];
    const float* Wih2 = (const float*)d_in[7];
    const float* Whh2 = (const float*)d_in[8];
    const float* bih2 = (const float*)d_in[9];
    const float* bhh2 = (const float*)d_in[10];
    const float* Wfc  = (const float*)d_in[11];
    const float* bfc  = (const float*)d_in[12];
    float* out = (float*)d_out;

    cudaFuncSetAttribute(k_gi1_tc, cudaFuncAttributeMaxDynamicSharedMemorySize, 81920);
    cudaFuncSetAttribute(k_steps,  cudaFuncAttributeMaxDynamicSharedMemorySize, 163840);

    void* bar_addr = nullptr;
    cudaGetSymbolAddress(&bar_addr, g_bars);
    cudaMemsetAsync(bar_addr, 0, 512 * sizeof(unsigned));

    k_prep_w<<<(G3_ * H_ + 255) / 256, 256>>>(Wih1, Whh1, Wih2, Whh2);
    k_prep_h<<<(B_ * H_ + 255) / 256, 256>>>(h1i, h2i);
    k_prep_x<<<(L_ * B_ * H_ + 255) / 256, 256>>>(x);

    k_gi1_tc<<<dim3(8, 8, 64), 256, 81920>>>(bih1);

    k_steps<<<128, 256, 163840>>>(h1i, h2i, bhh1, bih2, bhh2);

    k_fc<<<4096, 256>>>(Wfc, bfc, out);
    k_copy<<<(B_ * H_ + 255) / 256, 256>>>(out);
}

// round 9
// speedup vs baseline: 4.2728x; 1.0608x over previous
#include <cuda_runtime.h>
#include <cuda_bf16.h>
#include <math.h>
#include <stdint.h>

#define B_  512
#define T_  512
#define L_  64
#define H_  512
#define G3_ 1536
#define XW_ 575

// ------------------------- device scratch (no allocs) -----------------------
__device__ __align__(16) float g_GI1[(size_t)L_ * B_ * G3_];  // [t][b][3H]
__device__ __align__(16) float g_H1fin[(size_t)B_ * H_];      // final h1 (t=63)
__device__ __align__(16) float g_H2[(size_t)L_ * B_ * H_];    // fp32 h2 history
__device__ __align__(16) __nv_bfloat16 g_X2[(size_t)L_ * B_ * 1024]; // [t][b][hi|lo]
__device__ __align__(16) __nv_bfloat16 g_W0h[(size_t)G3_ * H_], g_W0l[(size_t)G3_ * H_];
__device__ __align__(16) __nv_bfloat16 g_W1h[(size_t)G3_ * H_], g_W1l[(size_t)G3_ * H_];
__device__ __align__(16) __nv_bfloat16 g_W2h[(size_t)G3_ * H_], g_W2l[(size_t)G3_ * H_];
__device__ __align__(16) __nv_bfloat16 g_W3h[(size_t)G3_ * H_], g_W3l[(size_t)G3_ * H_];
__device__ __align__(16) __nv_bfloat16 g_H1h[2][(size_t)B_ * H_], g_H1l[2][(size_t)B_ * H_];
__device__ __align__(16) __nv_bfloat16 g_H2h[2][(size_t)B_ * H_], g_H2l[2][(size_t)B_ * H_];
__device__ unsigned g_bars[512];   // per-m-group barrier counters (stride 32)

#define SLOT_  66560
#define EXOFF_ 199680           // 3 * SLOT_
#define SMTOT_ 225280           // EXOFF_ + 128*200

__device__ __forceinline__ float sigm(float v) { return 1.f / (1.f + __expf(-v)); }

__device__ __forceinline__ uint32_t smem_u32(const void* p) {
    uint32_t a;
    asm("{ .reg .u64 t; cvta.to.shared.u64 t, %1; cvt.u32.u64 %0, t; }" : "=r"(a) : "l"(p));
    return a;
}
__device__ __forceinline__ void ldsm4(uint32_t* r, uint32_t addr) {
    asm volatile("ldmatrix.sync.aligned.m8n8.x4.shared.b16 {%0,%1,%2,%3}, [%4];"
                 : "=r"(r[0]), "=r"(r[1]), "=r"(r[2]), "=r"(r[3]) : "r"(addr));
}
__device__ __forceinline__ void mma16816(float* c, const uint32_t* a, uint32_t b0, uint32_t b1) {
    asm volatile("mma.sync.aligned.m16n8k16.row.col.f32.bf16.bf16.f32 "
                 "{%0,%1,%2,%3}, {%4,%5,%6,%7}, {%8,%9}, {%0,%1,%2,%3};"
                 : "+f"(c[0]), "+f"(c[1]), "+f"(c[2]), "+f"(c[3])
                 : "r"(a[0]), "r"(a[1]), "r"(a[2]), "r"(a[3]), "r"(b0), "r"(b1));
}
__device__ __forceinline__ void split2(float a, __nv_bfloat16& h, __nv_bfloat16& l) {
    h = __float2bfloat16_rn(a);
    l = __float2bfloat16_rn(a - __bfloat162float(h));
}
__device__ __forceinline__ void cp16(uint32_t dst, const void* src) {
    asm volatile("cp.async.cg.shared.global [%0], [%1], 16;" :: "r"(dst), "l"(src));
}
__device__ __forceinline__ void cp_commit() {
    asm volatile("cp.async.commit_group;" ::: "memory");
}
template <int N> __device__ __forceinline__ void cp_wait() {
    asm volatile("cp.async.wait_group %0;" :: "n"(N) : "memory");
}
__device__ __forceinline__ void stage_cp(uint32_t dst, const __nv_bfloat16* src,
                                         int rows, int stride, int tid, int nthr) {
    for (int i = tid; i < rows * 4; i += nthr) {
        int r = i >> 2, q = i & 3;
        cp16(dst + r * 80 + q * 16, src + (size_t)r * stride + q * 8);
    }
}

// ---------------------------------------------------------------------------
// Prep kernels
// ---------------------------------------------------------------------------
__global__ __launch_bounds__(256) void k_prep_w(const float* __restrict__ W0,
                                                const float* __restrict__ W1,
                                                const float* __restrict__ W2,
                                                const float* __restrict__ W3) {
    size_t i = (size_t)blockIdx.x * 256 + threadIdx.x;
    if (i >= (size_t)G3_ * H_) return;
    __nv_bfloat16 h, l;
    split2(W0[i], h, l); g_W0h[i] = h; g_W0l[i] = l;
    split2(W1[i], h, l); g_W1h[i] = h; g_W1l[i] = l;
    split2(W2[i], h, l); g_W2h[i] = h; g_W2l[i] = l;
    split2(W3[i], h, l); g_W3h[i] = h; g_W3l[i] = l;
}

__global__ __launch_bounds__(256) void k_prep_h(const float* __restrict__ h1i,
                                                const float* __restrict__ h2i) {
    size_t i = (size_t)blockIdx.x * 256 + threadIdx.x;
    if (i >= (size_t)B_ * H_) return;
    __nv_bfloat16 h, l;
    split2(h1i[i], h, l); g_H1h[1][i] = h; g_H1l[1][i] = l;
    split2(h2i[i], h, l); g_H2h[1][i] = h; g_H2l[1][i] = l;
}

__global__ __launch_bounds__(256) void k_prep_x(const float* __restrict__ x) {
    size_t i = (size_t)blockIdx.x * 256 + threadIdx.x;
    if (i >= (size_t)L_ * B_ * H_) return;
    int k = (int)(i % H_);
    int b = (int)((i / H_) % B_);
    int t = (int)(i / ((size_t)B_ * H_));
    __nv_bfloat16 h, l;
    split2(x[(size_t)b * XW_ + t + k], h, l);
    size_t o = ((size_t)t * B_ + b) * 1024;
    g_X2[o + k] = h; g_X2[o + 512 + k] = l;
}

// ---------------------------------------------------------------------------
// k_gi1_tc: unchanged (M=64, N=3x64, 2 CTAs/SM, 2-stage)
// ---------------------------------------------------------------------------
__global__ __launch_bounds__(256, 2) void k_gi1_tc(const float* __restrict__ bias) {
    extern __shared__ char sm[];
    const uint32_t smb = smem_u32(sm);
    const int tid = threadIdx.x;
    const int j0 = blockIdx.x * 64;
    const int m0 = blockIdx.y * 64;
    const int t  = blockIdx.z;
    const __nv_bfloat16* A = g_X2 + ((size_t)t * B_ + m0) * 1024;

    auto stage = [&](int c) {
        const int k0 = c * 32;
        uint32_t d = smb + (uint32_t)(c & 1) * 40960;
        stage_cp(d,        A + k0,       64, 1024, tid, 256);
        stage_cp(d + 5120, A + 512 + k0, 64, 1024, tid, 256);
#pragma unroll
        for (int g = 0; g < 3; g++) {
            stage_cp(d + 10240 + g * 5120, g_W0h + (size_t)(g * 512 + j0) * H_ + k0, 64, H_, tid, 256);
            stage_cp(d + 25600 + g * 5120, g_W0l + (size_t)(g * 512 + j0) * H_ + k0, 64, H_, tid, 256);
        }
    };
    stage(0); cp_commit();

    const int wid = tid >> 5, lane = tid & 31;
    const int wm = (wid >> 2) * 32;
    const int wn = (wid & 3) * 16;
    const int arow = lane & 15, acol = (lane >> 4) * 8;
    const int brow = (lane & 7) + ((lane >> 4) << 3), bcol = ((lane >> 3) & 1) * 8;

    float acc[3][2][2][4];
#pragma unroll
    for (int g = 0; g < 3; g++)
#pragma unroll
        for (int mf = 0; mf < 2; mf++)
#pragma unroll
            for (int nf = 0; nf < 2; nf++)
#pragma unroll
                for (int q = 0; q < 4; q++) acc[g][mf][nf][q] = 0.f;

    for (int c = 0; c < 16; c++) {
        cp_wait<0>();
        __syncthreads();
        if (c + 1 < 16) stage(c + 1);
        cp_commit();
        const uint32_t Ab = smb + (uint32_t)(c & 1) * 40960;
#pragma unroll
        for (int h = 0; h < 2; h++) {
            const int c0 = h * 16;
            uint32_t aH[2][4], aL[2][4];
#pragma unroll
            for (int mf = 0; mf < 2; mf++) {
                uint32_t ao = ((wm + mf * 16 + arow) * 40 + c0 + acol) * 2;
                ldsm4(aH[mf], Ab + ao);
                ldsm4(aL[mf], Ab + 5120 + ao);
            }
            uint32_t bo = ((wn + brow) * 40 + c0 + bcol) * 2;
#pragma unroll
            for (int g = 0; g < 3; g++) {
                uint32_t bh[4], bl[4];
                ldsm4(bh, Ab + 10240 + g * 5120 + bo);
                ldsm4(bl, Ab + 25600 + g * 5120 + bo);
#pragma unroll
                for (int mf = 0; mf < 2; mf++)
#pragma unroll
                    for (int nf = 0; nf < 2; nf++) {
                        float* a = acc[g][mf][nf];
                        mma16816(a, aH[mf], bh[nf * 2], bh[nf * 2 + 1]);
                        mma16816(a, aH[mf], bl[nf * 2], bl[nf * 2 + 1]);
                        mma16816(a, aL[mf], bh[nf * 2], bh[nf * 2 + 1]);
                    }
            }
        }
    }

    const int row = lane >> 2, colp = (lane & 3) * 2;
    float* gi = g_GI1 + ((size_t)t * B_ + m0) * G3_;
#pragma unroll
    for (int g = 0; g < 3; g++)
#pragma unroll
        for (int mf = 0; mf < 2; mf++)
#pragma unroll
            for (int nf = 0; nf < 2; nf++) {
                int jg = j0 + wn + nf * 8 + colp;
                float2 bv = *(const float2*)(bias + g * 512 + jg);
#pragma unroll
                for (int hh = 0; hh < 2; hh++) {
                    int m = wm + mf * 16 + row + hh * 8;
                    float2 o;
                    o.x = acc[g][mf][nf][hh * 2 + 0] + bv.x;
                    o.y = acc[g][mf][nf][hh * 2 + 1] + bv.y;
                    *(float2*)(gi + (size_t)m * G3_ + g * 512 + jg) = o;
                }
            }
}

// ---------------------------------------------------------------------------
// k_steps: persistent merged recurrence with 3-way matmul warp specialization.
// 65 iterations; iteration i: h1(i)=GRU1(gi1(i),h1(i-1)) [skip i=64],
// h2(i-1)=GRU2(h1(i-1),h2(i-2)) [skip i=0]. 128 CTAs (16j x 8m), 384 thr.
// Warp groups (4 warps each, tile m32 x n16): G0: W_hh1 @ h1old -> L1 gates;
// G1: W_ih2 @ h1old -> L2 gi-part; G2: W_hh2 @ h2old -> L2 gh-part.
// Single 16-chunk K loop; ring 3 x 66560B: A1 hi/lo @0/5120, A2 @10240/15360,
// W1h@20480 W1l@28160 W2h@35840 W2l@43520 W3h@51200 W3l@58880 (3 gates x 2560).
// G1->G2 accumulator exchange via smem @EXOFF_. One per-m-group barrier/iter.
// Weights for chunks 0-1 prestaged BEFORE the barrier (step-invariant).
// ---------------------------------------------------------------------------
__global__ __launch_bounds__(384, 1) void k_steps(const float* __restrict__ h1i,
                                                  const float* __restrict__ h2i,
                                                  const float* __restrict__ bhh1,
                                                  const float* __restrict__ bih2,
                                                  const float* __restrict__ bhh2) {
    extern __shared__ char sm[];
    const uint32_t smb = smem_u32(sm);
    const int tid = threadIdx.x;
    const int bid = blockIdx.x;
    const int j0 = (bid & 15) * 32;
    const int m0 = (bid >> 4) * 64;
    const int grp = bid >> 4;
    const int wid = tid >> 5, lane = tid & 31;
    const int group = wid >> 2;            // 0:W1, 1:W2, 2:W3
    const int wg = wid & 3;
    const int wm = (wg & 1) * 32;
    const int wn16 = (wg >> 1) * 16;
    const int arow = lane & 15, acol = (lane >> 4) * 8;
    const int brow = (lane & 7) + ((lane >> 4) << 3), bcol = ((lane >> 3) & 1) * 8;
    const int row = lane >> 2, colp = (lane & 3) * 2;

    // biases per group (bs3 only used by G2)
    float2 bs0[2], bs1[2], bs2[2], bs3[2];
    // hidden-state carry: G0 -> h1, G2 -> h2
    float2 hp[2][2][2];
#pragma unroll
    for (int nf = 0; nf < 2; nf++) {
        int jg = j0 + wn16 + nf * 8 + colp;
        if (group == 0) {
            bs0[nf] = *(const float2*)(bhh1 + jg);
            bs1[nf] = *(const float2*)(bhh1 + 512 + jg);
            bs2[nf] = *(const float2*)(bhh1 + 1024 + jg);
            bs3[nf] = make_float2(0.f, 0.f);
        } else if (group == 2) {
            float2 u, v;
            u = *(const float2*)(bih2 + jg);       v = *(const float2*)(bhh2 + jg);
            bs0[nf] = make_float2(u.x + v.x, u.y + v.y);
            u = *(const float2*)(bih2 + 512 + jg); v = *(const float2*)(bhh2 + 512 + jg);
            bs1[nf] = make_float2(u.x + v.x, u.y + v.y);
            bs2[nf] = *(const float2*)(bih2 + 1024 + jg);
            bs3[nf] = *(const float2*)(bhh2 + 1024 + jg);
        } else {
            bs0[nf] = bs1[nf] = bs2[nf] = bs3[nf] = make_float2(0.f, 0.f);
        }
#pragma unroll
        for (int mf = 0; mf < 2; mf++)
#pragma unroll
            for (int hh = 0; hh < 2; hh++) {
                int m = m0 + wm + mf * 16 + row + hh * 8;
                const float* src = (group == 2) ? h2i : h1i;
                hp[mf][nf][hh] = *(const float2*)(src + (size_t)m * H_ + jg);
            }
    }

    auto stageW = [&](int c) {
        const int k0 = c * 32;
        uint32_t d = smb + (uint32_t)(c % 3) * SLOT_;
#pragma unroll
        for (int g = 0; g < 3; g++) {
            const size_t wo = (size_t)(g * 512 + j0) * H_ + k0;
            stage_cp(d + 20480 + g * 2560, g_W1h + wo, 32, H_, tid, 384);
            stage_cp(d + 28160 + g * 2560, g_W1l + wo, 32, H_, tid, 384);
            stage_cp(d + 35840 + g * 2560, g_W2h + wo, 32, H_, tid, 384);
            stage_cp(d + 43520 + g * 2560, g_W2l + wo, 32, H_, tid, 384);
            stage_cp(d + 51200 + g * 2560, g_W3h + wo, 32, H_, tid, 384);
            stage_cp(d + 58880 + g * 2560, g_W3l + wo, 32, H_, tid, 384);
        }
    };
    auto stageA = [&](int c, int op1, int op2) {
        const int k0 = c * 32;
        uint32_t d = smb + (uint32_t)(c % 3) * SLOT_;
        stage_cp(d,         g_H1h[op1] + (size_t)m0 * H_ + k0, 64, H_, tid, 384);
        stage_cp(d + 5120,  g_H1l[op1] + (size_t)m0 * H_ + k0, 64, H_, tid, 384);
        stage_cp(d + 10240, g_H2h[op2] + (size_t)m0 * H_ + k0, 64, H_, tid, 384);
        stage_cp(d + 15360, g_H2l[op2] + (size_t)m0 * H_ + k0, 64, H_, tid, 384);
    };

    // bootstrap: weights of chunks 0,1 (A of iter 0 comes from prep_h — visible)
    stageW(0); cp_commit();
    stageW(1); cp_commit();

    const uint32_t abase_off = (group == 2) ? 10240u : 0u;
    const uint32_t wbase_off = 20480u + (uint32_t)group * 15360u;

    unsigned barT = 0;
    for (int i = 0; i <= L_; i++) {
        const int op1 = (i + 1) & 1;
        const int op2 = i & 1;

        stageA(0, op1, op2); cp_commit();
        stageA(1, op1, op2); cp_commit();

        float acc[3][2][2][4];
#pragma unroll
        for (int g = 0; g < 3; g++)
#pragma unroll
            for (int mf = 0; mf < 2; mf++)
#pragma unroll
                for (int nf = 0; nf < 2; nf++)
#pragma unroll
                    for (int q = 0; q < 4; q++) acc[g][mf][nf][q] = 0.f;

        for (int gc = 0; gc < 16; gc++) {
            cp_wait<1>();
            __syncthreads();
            if (gc + 2 < 16) { stageW(gc + 2); stageA(gc + 2, op1, op2); }
            cp_commit();
            const uint32_t Ab = smb + (uint32_t)(gc % 3) * SLOT_;
            const uint32_t abase = Ab + abase_off;
            const uint32_t wbase = Ab + wbase_off;
#pragma unroll
            for (int h = 0; h < 2; h++) {
                const int c0 = h * 16;
                uint32_t aH[2][4], aL[2][4];
#pragma unroll
                for (int mf = 0; mf < 2; mf++) {
                    uint32_t ao = ((wm + mf * 16 + arow) * 40 + c0 + acol) * 2;
                    ldsm4(aH[mf], abase + ao);
                    ldsm4(aL[mf], abase + 5120 + ao);
                }
                const uint32_t bo = ((wn16 + brow) * 40 + c0 + bcol) * 2;
#pragma unroll
                for (int g = 0; g < 3; g++) {
                    uint32_t bh[4], bl[4];
                    ldsm4(bh, wbase + g * 2560 + bo);
                    ldsm4(bl, wbase + 7680 + g * 2560 + bo);
#pragma unroll
                    for (int mf = 0; mf < 2; mf++)
#pragma unroll
                        for (int nf = 0; nf < 2; nf++) {
                            float* a = acc[g][mf][nf];
                            mma16816(a, aH[mf], bh[nf * 2], bh[nf * 2 + 1]);
                            mma16816(a, aH[mf], bl[nf * 2], bl[nf * 2 + 1]);
                            mma16816(a, aL[mf], bh[nf * 2], bh[nf * 2 + 1]);
                        }
                }
            }
        }

        // chunk-15 ldsm complete in all warps before slot0 is restaged
        __syncthreads();

        // G1 publishes its L2 gi-part accumulators
        if (group == 1) {
            float* ex = (float*)(sm + EXOFF_) + (wg * 32 + lane) * 50;
#pragma unroll
            for (int g = 0; g < 3; g++)
#pragma unroll
                for (int mf = 0; mf < 2; mf++)
#pragma unroll
                    for (int nf = 0; nf < 2; nf++)
#pragma unroll
                        for (int q = 0; q < 4; q++)
                            ex[((g * 2 + mf) * 2 + nf) * 4 + q] = acc[g][mf][nf][q];
        }
        // prestage next iteration's step-invariant weights (slots 0,1 free now)
        if (i < L_) { stageW(0); cp_commit(); stageW(1); cp_commit(); }
        __syncthreads();

        // ---- G0: layer-1 epilogue -> h1(i) ----
        if (group == 0 && i < L_) {
            __nv_bfloat16* hhN = g_H1h[i & 1];
            __nv_bfloat16* hlN = g_H1l[i & 1];
#pragma unroll
            for (int mf = 0; mf < 2; mf++)
#pragma unroll
                for (int nf = 0; nf < 2; nf++) {
                    int jg = j0 + wn16 + nf * 8 + colp;
#pragma unroll
                    for (int hh = 0; hh < 2; hh++) {
                        int m = m0 + wm + mf * 16 + row + hh * 8;
                        const float* gb = g_GI1 + ((size_t)i * B_ + m) * G3_;
                        float2 gr = *(const float2*)(gb + jg);
                        float2 gz = *(const float2*)(gb + 512 + jg);
                        float2 gn = *(const float2*)(gb + 1024 + jg);
                        float r0 = sigm(gr.x + acc[0][mf][nf][hh * 2] + bs0[nf].x);
                        float r1 = sigm(gr.y + acc[0][mf][nf][hh * 2 + 1] + bs0[nf].y);
                        float z0 = sigm(gz.x + acc[1][mf][nf][hh * 2] + bs1[nf].x);
                        float z1 = sigm(gz.y + acc[1][mf][nf][hh * 2 + 1] + bs1[nf].y);
                        float n0 = tanhf(gn.x + r0 * (acc[2][mf][nf][hh * 2] + bs2[nf].x));
                        float n1 = tanhf(gn.y + r1 * (acc[2][mf][nf][hh * 2 + 1] + bs2[nf].y));
                        float h0 = (1.f - z0) * n0 + z0 * hp[mf][nf][hh].x;
                        float h1 = (1.f - z1) * n1 + z1 * hp[mf][nf][hh].y;
                        hp[mf][nf][hh] = make_float2(h0, h1);
                        __nv_bfloat16 x0, y0, x1, y1;
                        split2(h0, x0, y0); split2(h1, x1, y1);
                        __nv_bfloat162 hv; hv.x = x0; hv.y = x1;
                        __nv_bfloat162 lv; lv.x = y0; lv.y = y1;
                        *(__nv_bfloat162*)(hhN + (size_t)m * H_ + jg) = hv;
                        *(__nv_bfloat162*)(hlN + (size_t)m * H_ + jg) = lv;
                        if (i == L_ - 1)
                            *(float2*)(g_H1fin + (size_t)m * H_ + jg) = make_float2(h0, h1);
                    }
                }
        }

        // ---- G2: layer-2 epilogue -> h2(i-1) ----
        if (group == 2 && i > 0) {
            const int t2 = i - 1;
            const float* ex = (const float*)(sm + EXOFF_) + (wg * 32 + lane) * 50;
            float* h2new = g_H2 + (size_t)t2 * B_ * H_;
            __nv_bfloat16* hhN = g_H2h[t2 & 1];
            __nv_bfloat16* hlN = g_H2l[t2 & 1];
#pragma unroll
            for (int mf = 0; mf < 2; mf++)
#pragma unroll
                for (int nf = 0; nf < 2; nf++) {
                    int jg = j0 + wn16 + nf * 8 + colp;
#pragma unroll
                    for (int hh = 0; hh < 2; hh++) {
                        int m = m0 + wm + mf * 16 + row + hh * 8;
                        int er = ((0 * 2 + mf) * 2 + nf) * 4 + hh * 2;
                        int ez = ((1 * 2 + mf) * 2 + nf) * 4 + hh * 2;
                        int en = ((2 * 2 + mf) * 2 + nf) * 4 + hh * 2;
                        float r0 = sigm(acc[0][mf][nf][hh * 2] + ex[er] + bs0[nf].x);
                        float r1 = sigm(acc[0][mf][nf][hh * 2 + 1] + ex[er + 1] + bs0[nf].y);
                        float z0 = sigm(acc[1][mf][nf][hh * 2] + ex[ez] + bs1[nf].x);
                        float z1 = sigm(acc[1][mf][nf][hh * 2 + 1] + ex[ez + 1] + bs1[nf].y);
                        float n0 = tanhf(ex[en] + bs2[nf].x + r0 * (acc[2][mf][nf][hh * 2] + bs3[nf].x));
                        float n1 = tanhf(ex[en + 1] + bs2[nf].y + r1 * (acc[2][mf][nf][hh * 2 + 1] + bs3[nf].y));
                        float h0 = (1.f - z0) * n0 + z0 * hp[mf][nf][hh].x;
                        float h1 = (1.f - z1) * n1 + z1 * hp[mf][nf][hh].y;
                        hp[mf][nf][hh] = make_float2(h0, h1);
                        *(float2*)(h2new + (size_t)m * H_ + jg) = make_float2(h0, h1);
                        __nv_bfloat16 x0, y0, x1, y1;
                        split2(h0, x0, y0); split2(h1, x1, y1);
                        __nv_bfloat162 hv; hv.x = x0; hv.y = x1;
                        __nv_bfloat162 lv; lv.x = y0; lv.y = y1;
                        *(__nv_bfloat162*)(hhN + (size_t)m * H_ + jg) = hv;
                        *(__nv_bfloat162*)(hlN + (size_t)m * H_ + jg) = lv;
                    }
                }
        }

        // ---- per-m-group barrier ----
        __threadfence();
        __syncthreads();
        if (tid == 0) atomicAdd(&g_bars[grp * 32], 1u);
        barT += 16;
        if (tid == 0) {
            while (*(volatile unsigned*)&g_bars[grp * 32] < barT) { }
        }
        __syncthreads();
    }
}

// ---------------------------------------------------------------------------
__global__ __launch_bounds__(256) void k_fc(const float* __restrict__ Wfc,
                                            const float* __restrict__ bfc,
                                            float* __restrict__ out) {
    int w = (blockIdx.x * 256 + threadIdx.x) >> 5;
    int lane = threadIdx.x & 31;
    int b = w >> 6, tt = w & 63;
    const float* h = g_H2 + ((size_t)tt * B_ + b) * H_;
    float s = 0.f;
#pragma unroll
    for (int q = 0; q < H_ / 32; q++) s += h[lane + 32 * q] * Wfc[lane + 32 * q];
#pragma unroll
    for (int off = 16; off; off >>= 1) s += __shfl_down_sync(0xffffffffu, s, off);
    if (lane == 0) out[(size_t)b * L_ + tt] = s + bfc[0];
}

__global__ __launch_bounds__(256) void k_copy(float* __restrict__ out) {
    int i = blockIdx.x * 256 + threadIdx.x;
    const int n = B_ * H_;
    if (i < n) {
        out[B_ * L_ + i] = g_H1fin[i];
        out[B_ * L_ + n + i] = g_H2[(size_t)(L_ - 1) * n + i];
    }
}

// ---------------------------------------------------------------------------
extern "C" void kernel_launch(void* const* d_in, const int* in_sizes, int n_in,
                              void* d_out, int out_size) {
    const float* x    = (const float*)d_in[0];
    const float* h1i  = (const float*)d_in[1];
    const float* h2i  = (const float*)d_in[2];
    const float* Wih1 = (const float*)d_in[3];
    const float* Whh1 = (const float*)d_in[4];
    const float* bih1 = (const float*)d_in[5];
    const float* bhh1 = (const float*)d_in[6];
    const float* Wih2 = (const float*)d_in[7];
    const float* Whh2 = (const float*)d_in[8];
    const float* bih2 = (const float*)d_in[9];
    const float* bhh2 = (const float*)d_in[10];
    const float* Wfc  = (const float*)d_in[11];
    const float* bfc  = (const float*)d_in[12];
    float* out = (float*)d_out;

    cudaFuncSetAttribute(k_gi1_tc, cudaFuncAttributeMaxDynamicSharedMemorySize, 81920);
    cudaFuncSetAttribute(k_steps,  cudaFuncAttributeMaxDynamicSharedMemorySize, SMTOT_);

    void* bar_addr = nullptr;
    cudaGetSymbolAddress(&bar_addr, g_bars);
    cudaMemsetAsync(bar_addr, 0, 512 * sizeof(unsigned));

    k_prep_w<<<(G3_ * H_ + 255) / 256, 256>>>(Wih1, Whh1, Wih2, Whh2);
    k_prep_h<<<(B_ * H_ + 255) / 256, 256>>>(h1i, h2i);
    k_prep_x<<<(L_ * B_ * H_ + 255) / 256, 256>>>(x);

    k_gi1_tc<<<dim3(8, 8, 64), 256, 81920>>>(bih1);

    k_steps<<<128, 384, SMTOT_>>>(h1i, h2i, bhh1, bih2, bhh2);

    k_fc<<<4096, 256>>>(Wfc, bfc, out);
    k_copy<<<(B_ * H_ + 255) / 256, 256>>>(out);
}

// round 12
// speedup vs baseline: 4.6099x; 1.0789x over previous
#include <cuda_runtime.h>
#include <cuda_bf16.h>
#include <math.h>
#include <stdint.h>

#define B_  512
#define T_  512
#define L_  64
#define H_  512
#define G3_ 1536
#define XW_ 575

#define SLOT_  92160
#define SMTOT_ 184320

// ------------------------- device scratch (no allocs) -----------------------
__device__ __align__(16) float g_H1fin[(size_t)B_ * H_];
__device__ __align__(16) float g_H2[(size_t)L_ * B_ * H_];
__device__ __align__(16) __nv_bfloat16 g_X2[(size_t)L_ * B_ * 1024]; // [t][b][hi|lo]
__device__ __align__(16) __nv_bfloat16 g_W0h[(size_t)G3_ * H_], g_W0l[(size_t)G3_ * H_];
__device__ __align__(16) __nv_bfloat16 g_W1h[(size_t)G3_ * H_], g_W1l[(size_t)G3_ * H_];
__device__ __align__(16) __nv_bfloat16 g_W2h[(size_t)G3_ * H_], g_W2l[(size_t)G3_ * H_];
__device__ __align__(16) __nv_bfloat16 g_W3h[(size_t)G3_ * H_], g_W3l[(size_t)G3_ * H_];
__device__ __align__(16) __nv_bfloat16 g_H1h[2][(size_t)B_ * H_], g_H1l[2][(size_t)B_ * H_];
__device__ __align__(16) __nv_bfloat16 g_H2h[2][(size_t)B_ * H_], g_H2l[2][(size_t)B_ * H_];
__device__ unsigned g_bars[512];

__device__ __forceinline__ float sigm(float v) { return 1.f / (1.f + __expf(-v)); }

__device__ __forceinline__ uint32_t smem_u32(const void* p) {
    uint32_t a;
    asm("{ .reg .u64 t; cvta.to.shared.u64 t, %1; cvt.u32.u64 %0, t; }" : "=r"(a) : "l"(p));
    return a;
}
__device__ __forceinline__ void ldsm4(uint32_t* r, uint32_t addr) {
    asm volatile("ldmatrix.sync.aligned.m8n8.x4.shared.b16 {%0,%1,%2,%3}, [%4];"
                 : "=r"(r[0]), "=r"(r[1]), "=r"(r[2]), "=r"(r[3]) : "r"(addr));
}
__device__ __forceinline__ void mma16816(float* c, const uint32_t* a, uint32_t b0, uint32_t b1) {
    asm volatile("mma.sync.aligned.m16n8k16.row.col.f32.bf16.bf16.f32 "
                 "{%0,%1,%2,%3}, {%4,%5,%6,%7}, {%8,%9}, {%0,%1,%2,%3};"
                 : "+f"(c[0]), "+f"(c[1]), "+f"(c[2]), "+f"(c[3])
                 : "r"(a[0]), "r"(a[1]), "r"(a[2]), "r"(a[3]), "r"(b0), "r"(b1));
}
__device__ __forceinline__ void split2(float a, __nv_bfloat16& h, __nv_bfloat16& l) {
    h = __float2bfloat16_rn(a);
    l = __float2bfloat16_rn(a - __bfloat162float(h));
}
__device__ __forceinline__ void cp16(uint32_t dst, const void* src) {
    asm volatile("cp.async.cg.shared.global [%0], [%1], 16;" :: "r"(dst), "l"(src));
}
__device__ __forceinline__ void cp_commit() {
    asm volatile("cp.async.commit_group;" ::: "memory");
}
template <int N> __device__ __forceinline__ void cp_wait() {
    asm volatile("cp.async.wait_group %0;" :: "n"(N) : "memory");
}
__device__ __forceinline__ void stage_cp(uint32_t dst, const __nv_bfloat16* src,
                                         int rows, int stride, int tid, int nthr) {
    for (int i = tid; i < rows * 4; i += nthr) {
        int r = i >> 2, q = i & 3;
        cp16(dst + r * 80 + q * 16, src + (size_t)r * stride + q * 8);
    }
}

// ---------------------------------------------------------------------------
// Prep kernels
// ---------------------------------------------------------------------------
__global__ __launch_bounds__(256) void k_prep_w(const float* __restrict__ W0,
                                                const float* __restrict__ W1,
                                                const float* __restrict__ W2,
                                                const float* __restrict__ W3) {
    size_t i = (size_t)blockIdx.x * 256 + threadIdx.x;
    if (i >= (size_t)G3_ * H_) return;
    __nv_bfloat16 h, l;
    split2(W0[i], h, l); g_W0h[i] = h; g_W0l[i] = l;
    split2(W1[i], h, l); g_W1h[i] = h; g_W1l[i] = l;
    split2(W2[i], h, l); g_W2h[i] = h; g_W2l[i] = l;
    split2(W3[i], h, l); g_W3h[i] = h; g_W3l[i] = l;
}

__global__ __launch_bounds__(256) void k_prep_h(const float* __restrict__ h1i,
                                                const float* __restrict__ h2i) {
    size_t i = (size_t)blockIdx.x * 256 + threadIdx.x;
    if (i >= (size_t)B_ * H_) return;
    __nv_bfloat16 h, l;
    split2(h1i[i], h, l); g_H1h[1][i] = h; g_H1l[1][i] = l;
    split2(h2i[i], h, l); g_H2h[1][i] = h; g_H2l[1][i] = l;
}

__global__ __launch_bounds__(256) void k_prep_x(const float* __restrict__ x) {
    size_t i = (size_t)blockIdx.x * 256 + threadIdx.x;
    if (i >= (size_t)L_ * B_ * H_) return;
    int k = (int)(i % H_);
    int b = (int)((i / H_) % B_);
    int t = (int)(i / ((size_t)B_ * H_));
    __nv_bfloat16 h, l;
    split2(x[(size_t)b * XW_ + t + k], h, l);
    size_t o = ((size_t)t * B_ + b) * 1024;
    g_X2[o + k] = h; g_X2[o + 512 + k] = l;
}

// ---------------------------------------------------------------------------
// k_steps: persistent recurrence with 4-way matmul warp specialization.
// 65 iterations; iter i: h1(i)=GRU1(gi(i),h1(i-1)) [i<64],
// h2(i-1)=GRU2(h1(i-1),h2(i-2)) [i>0]. 128 CTAs (16j x 8m), 512 thr.
// Groups (4 warps, tile m32 x n16): G0: W_hh1@h1old (L1 gates);
// G1: W_ih2@h1old (L2 gi-part); G2: W_hh2@h2old (L2 gh-part);
// G3: W_ih1@x(i)  (L1 gi-part, replaces the separate gi1 kernel).
// Ring: 2 slots x 92160B. Slot: A1h@0 A1l@5120 A2h@10240 A2l@15360
//   AXh@20480 AXl@25600 | W @30720 + grp*15360 (hi 3x2560, lo +7680).
// Exchanges (post-K-loop, in dead A-regions): EX1 (G1->G2) @ slot0,
// EX2 (G3->G0) @ slot1. One per-m-group barrier per iteration.
// ---------------------------------------------------------------------------
__global__ __launch_bounds__(512, 1) void k_steps(const float* __restrict__ h1i,
                                                  const float* __restrict__ h2i,
                                                  const float* __restrict__ bih1,
                                                  const float* __restrict__ bhh1,
                                                  const float* __restrict__ bih2,
                                                  const float* __restrict__ bhh2) {
    extern __shared__ char sm[];
    const uint32_t smb = smem_u32(sm);
    const int tid = threadIdx.x;
    const int bid = blockIdx.x;
    const int j0 = (bid & 15) * 32;
    const int m0 = (bid >> 4) * 64;
    const int grp = bid >> 4;
    const int wid = tid >> 5, lane = tid & 31;
    const int group = wid >> 2;            // 0:W1, 1:W2, 2:W3, 3:W0(gi)
    const int wg = wid & 3;
    const int wm = (wg & 1) * 32;
    const int wn16 = (wg >> 1) * 16;
    const int arow = lane & 15, acol = (lane >> 4) * 8;
    const int brow = (lane & 7) + ((lane >> 4) << 3), bcol = ((lane >> 3) & 1) * 8;
    const int row = lane >> 2, colp = (lane & 3) * 2;

    // biases per group
    float2 bs0[2], bs1[2], bs2[2], bs3[2];
    float2 hp[2][2][2];   // G0 -> h1 carry, G2 -> h2 carry
#pragma unroll
    for (int nf = 0; nf < 2; nf++) {
        int jg = j0 + wn16 + nf * 8 + colp;
        float2 u, v;
        if (group == 0) {
            u = *(const float2*)(bih1 + jg);        v = *(const float2*)(bhh1 + jg);
            bs0[nf] = make_float2(u.x + v.x, u.y + v.y);
            u = *(const float2*)(bih1 + 512 + jg);  v = *(const float2*)(bhh1 + 512 + jg);
            bs1[nf] = make_float2(u.x + v.x, u.y + v.y);
            bs2[nf] = *(const float2*)(bih1 + 1024 + jg);
            bs3[nf] = *(const float2*)(bhh1 + 1024 + jg);
        } else if (group == 2) {
            u = *(const float2*)(bih2 + jg);        v = *(const float2*)(bhh2 + jg);
            bs0[nf] = make_float2(u.x + v.x, u.y + v.y);
            u = *(const float2*)(bih2 + 512 + jg);  v = *(const float2*)(bhh2 + 512 + jg);
            bs1[nf] = make_float2(u.x + v.x, u.y + v.y);
            bs2[nf] = *(const float2*)(bih2 + 1024 + jg);
            bs3[nf] = *(const float2*)(bhh2 + 1024 + jg);
        } else {
            bs0[nf] = bs1[nf] = bs2[nf] = bs3[nf] = make_float2(0.f, 0.f);
        }
#pragma unroll
        for (int mf = 0; mf < 2; mf++)
#pragma unroll
            for (int hh = 0; hh < 2; hh++) {
                int m = m0 + wm + mf * 16 + row + hh * 8;
                const float* src = (group == 2) ? h2i : h1i;
                hp[mf][nf][hh] = *(const float2*)(src + (size_t)m * H_ + jg);
            }
    }

    auto stageW = [&](int c) {
        const int k0 = c * 32;
        uint32_t d = smb + (uint32_t)(c & 1) * SLOT_ + 30720u;
#pragma unroll
        for (int g = 0; g < 3; g++) {
            const size_t wo = (size_t)(g * 512 + j0) * H_ + k0;
            stage_cp(d +     0 + g * 2560, g_W1h + wo, 32, H_, tid, 512);
            stage_cp(d +  7680 + g * 2560, g_W1l + wo, 32, H_, tid, 512);
            stage_cp(d + 15360 + g * 2560, g_W2h + wo, 32, H_, tid, 512);
            stage_cp(d + 23040 + g * 2560, g_W2l + wo, 32, H_, tid, 512);
            stage_cp(d + 30720 + g * 2560, g_W3h + wo, 32, H_, tid, 512);
            stage_cp(d + 38400 + g * 2560, g_W3l + wo, 32, H_, tid, 512);
            stage_cp(d + 46080 + g * 2560, g_W0h + wo, 32, H_, tid, 512);
            stage_cp(d + 53760 + g * 2560, g_W0l + wo, 32, H_, tid, 512);
        }
    };
    auto stageA = [&](int c, int op1, int op2, int ti) {
        const int k0 = c * 32;
        uint32_t d = smb + (uint32_t)(c & 1) * SLOT_;
        stage_cp(d,         g_H1h[op1] + (size_t)m0 * H_ + k0, 64, H_, tid, 512);
        stage_cp(d + 5120,  g_H1l[op1] + (size_t)m0 * H_ + k0, 64, H_, tid, 512);
        stage_cp(d + 10240, g_H2h[op2] + (size_t)m0 * H_ + k0, 64, H_, tid, 512);
        stage_cp(d + 15360, g_H2l[op2] + (size_t)m0 * H_ + k0, 64, H_, tid, 512);
        const __nv_bfloat16* X = g_X2 + ((size_t)ti * B_ + m0) * 1024;
        stage_cp(d + 20480, X + k0,       64, 1024, tid, 512);
        stage_cp(d + 25600, X + 512 + k0, 64, 1024, tid, 512);
    };

    const uint32_t abase_off = (group == 2) ? 10240u : ((group == 3) ? 20480u : 0u);
    const uint32_t wbase_off = 30720u + (uint32_t)group * 15360u;
    const uint32_t ex1 = smb;            // slot0 A-region (G1 -> G2)
    const uint32_t ex2 = smb + SLOT_;    // slot1 A-region (G3 -> G0)
    const int exi = ((wg * 32 + lane) * 48) * 4;   // byte offset of this thread's 48 floats

    // bootstrap: chunk-0 weights
    stageW(0); cp_commit();

    unsigned barT = 0;
    for (int i = 0; i <= L_; i++) {
        const int op1 = (i + 1) & 1;
        const int op2 = i & 1;
        const int ti = (i < L_) ? i : 0;

        stageA(0, op1, op2, ti); cp_commit();

        float acc[3][2][2][4];
#pragma unroll
        for (int g = 0; g < 3; g++)
#pragma unroll
            for (int mf = 0; mf < 2; mf++)
#pragma unroll
                for (int nf = 0; nf < 2; nf++)
#pragma unroll
                    for (int q = 0; q < 4; q++) acc[g][mf][nf][q] = 0.f;

        for (int gc = 0; gc < 16; gc++) {
            cp_wait<0>();
            __syncthreads();
            if (gc + 1 < 16) { stageW(gc + 1); stageA(gc + 1, op1, op2, ti); }
            cp_commit();
            const uint32_t Ab = smb + (uint32_t)(gc & 1) * SLOT_;
            const uint32_t abase = Ab + abase_off;
            const uint32_t wbase = Ab + wbase_off;
#pragma unroll
            for (int h = 0; h < 2; h++) {
                const int c0 = h * 16;
                uint32_t aH[2][4], aL[2][4];
#pragma unroll
                for (int mf = 0; mf < 2; mf++) {
                    uint32_t ao = ((wm + mf * 16 + arow) * 40 + c0 + acol) * 2;
                    ldsm4(aH[mf], abase + ao);
                    ldsm4(aL[mf], abase + 5120 + ao);
                }
                const uint32_t bo = ((wn16 + brow) * 40 + c0 + bcol) * 2;
#pragma unroll
                for (int g = 0; g < 3; g++) {
                    uint32_t bh[4], bl[4];
                    ldsm4(bh, wbase + g * 2560 + bo);
                    ldsm4(bl, wbase + 7680 + g * 2560 + bo);
#pragma unroll
                    for (int mf = 0; mf < 2; mf++)
#pragma unroll
                        for (int nf = 0; nf < 2; nf++) {
                            float* a = acc[g][mf][nf];
                            mma16816(a, aH[mf], bh[nf * 2], bh[nf * 2 + 1]);
                            mma16816(a, aH[mf], bl[nf * 2], bl[nf * 2 + 1]);
                            mma16816(a, aL[mf], bh[nf * 2], bh[nf * 2 + 1]);
                        }
                }
            }
        }
        cp_wait<0>();
        __syncthreads();   // all ldsm done; A-regions now dead -> exchanges

        if (group == 1) {
            float* ex = (float*)(uintptr_t)0;  // placeholder; use smem store below
            (void)ex;
#pragma unroll
            for (int g = 0; g < 3; g++)
#pragma unroll
                for (int mf = 0; mf < 2; mf++)
#pragma unroll
                    for (int nf = 0; nf < 2; nf++)
#pragma unroll
                        for (int q = 0; q < 4; q++) {
                            uint32_t addr = ex1 + exi + (((g * 2 + mf) * 2 + nf) * 4 + q) * 4;
                            asm volatile("st.shared.f32 [%0], %1;" :: "r"(addr), "f"(acc[g][mf][nf][q]));
                        }
        }
        if (group == 3) {
#pragma unroll
            for (int g = 0; g < 3; g++)
#pragma unroll
                for (int mf = 0; mf < 2; mf++)
#pragma unroll
                    for (int nf = 0; nf < 2; nf++)
#pragma unroll
                        for (int q = 0; q < 4; q++) {
                            uint32_t addr = ex2 + exi + (((g * 2 + mf) * 2 + nf) * 4 + q) * 4;
                            asm volatile("st.shared.f32 [%0], %1;" :: "r"(addr), "f"(acc[g][mf][nf][q]));
                        }
        }
        // prestage next iteration's chunk-0 weights (slot0 W region is dead)
        if (i < L_) { stageW(0); cp_commit(); }
        __syncthreads();   // exchanges visible

        // ---- G0: layer-1 epilogue -> h1(i), consuming G3's gi accumulators ----
        if (group == 0 && i < L_) {
            __nv_bfloat16* hhN = g_H1h[i & 1];
            __nv_bfloat16* hlN = g_H1l[i & 1];
#pragma unroll
            for (int mf = 0; mf < 2; mf++)
#pragma unroll
                for (int nf = 0; nf < 2; nf++) {
                    int jg = j0 + wn16 + nf * 8 + colp;
#pragma unroll
                    for (int hh = 0; hh < 2; hh++) {
                        int m = m0 + wm + mf * 16 + row + hh * 8;
                        float exv[6];
#pragma unroll
                        for (int g = 0; g < 3; g++)
#pragma unroll
                            for (int q = 0; q < 2; q++) {
                                uint32_t addr = ex2 + exi + (((g * 2 + mf) * 2 + nf) * 4 + hh * 2 + q) * 4;
                                asm volatile("ld.shared.f32 %0, [%1];" : "=f"(exv[g * 2 + q]) : "r"(addr));
                            }
                        float r0 = sigm(exv[0] + acc[0][mf][nf][hh * 2] + bs0[nf].x);
                        float r1 = sigm(exv[1] + acc[0][mf][nf][hh * 2 + 1] + bs0[nf].y);
                        float z0 = sigm(exv[2] + acc[1][mf][nf][hh * 2] + bs1[nf].x);
                        float z1 = sigm(exv[3] + acc[1][mf][nf][hh * 2 + 1] + bs1[nf].y);
                        float n0 = tanhf(exv[4] + bs2[nf].x + r0 * (acc[2][mf][nf][hh * 2] + bs3[nf].x));
                        float n1 = tanhf(exv[5] + bs2[nf].y + r1 * (acc[2][mf][nf][hh * 2 + 1] + bs3[nf].y));
                        float h0 = (1.f - z0) * n0 + z0 * hp[mf][nf][hh].x;
                        float h1 = (1.f - z1) * n1 + z1 * hp[mf][nf][hh].y;
                        hp[mf][nf][hh] = make_float2(h0, h1);
                        __nv_bfloat16 x0, y0, x1, y1;
                        split2(h0, x0, y0); split2(h1, x1, y1);
                        __nv_bfloat162 hv; hv.x = x0; hv.y = x1;
                        __nv_bfloat162 lv; lv.x = y0; lv.y = y1;
                        *(__nv_bfloat162*)(hhN + (size_t)m * H_ + jg) = hv;
                        *(__nv_bfloat162*)(hlN + (size_t)m * H_ + jg) = lv;
                        if (i == L_ - 1)
                            *(float2*)(g_H1fin + (size_t)m * H_ + jg) = make_float2(h0, h1);
                    }
                }
        }

        // ---- G2: layer-2 epilogue -> h2(i-1), consuming G1's gi2 accumulators ----
        if (group == 2 && i > 0) {
            const int t2 = i - 1;
            float* h2new = g_H2 + (size_t)t2 * B_ * H_;
            __nv_bfloat16* hhN = g_H2h[t2 & 1];
            __nv_bfloat16* hlN = g_H2l[t2 & 1];
#pragma unroll
            for (int mf = 0; mf < 2; mf++)
#pragma unroll
                for (int nf = 0; nf < 2; nf++) {
                    int jg = j0 + wn16 + nf * 8 + colp;
#pragma unroll
                    for (int hh = 0; hh < 2; hh++) {
                        int m = m0 + wm + mf * 16 + row + hh * 8;
                        float exv[6];
#pragma unroll
                        for (int g = 0; g < 3; g++)
#pragma unroll
                            for (int q = 0; q < 2; q++) {
                                uint32_t addr = ex1 + exi + (((g * 2 + mf) * 2 + nf) * 4 + hh * 2 + q) * 4;
                                asm volatile("ld.shared.f32 %0, [%1];" : "=f"(exv[g * 2 + q]) : "r"(addr));
                            }
                        float r0 = sigm(acc[0][mf][nf][hh * 2] + exv[0] + bs0[nf].x);
                        float r1 = sigm(acc[0][mf][nf][hh * 2 + 1] + exv[1] + bs0[nf].y);
                        float z0 = sigm(acc[1][mf][nf][hh * 2] + exv[2] + bs1[nf].x);
                        float z1 = sigm(acc[1][mf][nf][hh * 2 + 1] + exv[3] + bs1[nf].y);
                        float n0 = tanhf(exv[4] + bs2[nf].x + r0 * (acc[2][mf][nf][hh * 2] + bs3[nf].x));
                        float n1 = tanhf(exv[5] + bs2[nf].y + r1 * (acc[2][mf][nf][hh * 2 + 1] + bs3[nf].y));
                        float h0 = (1.f - z0) * n0 + z0 * hp[mf][nf][hh].x;
                        float h1 = (1.f - z1) * n1 + z1 * hp[mf][nf][hh].y;
                        hp[mf][nf][hh] = make_float2(h0, h1);
                        *(float2*)(h2new + (size_t)m * H_ + jg) = make_float2(h0, h1);
                        __nv_bfloat16 x0, y0, x1, y1;
                        split2(h0, x0, y0); split2(h1, x1, y1);
                        __nv_bfloat162 hv; hv.x = x0; hv.y = x1;
                        __nv_bfloat162 lv; lv.x = y0; lv.y = y1;
                        *(__nv_bfloat162*)(hhN + (size_t)m * H_ + jg) = hv;
                        *(__nv_bfloat162*)(hlN + (size_t)m * H_ + jg) = lv;
                    }
                }
        }

        // ---- per-m-group barrier ----
        __threadfence();
        __syncthreads();
        if (tid == 0) atomicAdd(&g_bars[grp * 32], 1u);
        barT += 16;
        if (tid == 0) {
            while (*(volatile unsigned*)&g_bars[grp * 32] < barT) { }
        }
        __syncthreads();
    }
}

// ---------------------------------------------------------------------------
__global__ __launch_bounds__(256) void k_fc(const float* __restrict__ Wfc,
                                            const float* __restrict__ bfc,
                                            float* __restrict__ out) {
    int w = (blockIdx.x * 256 + threadIdx.x) >> 5;
    int lane = threadIdx.x & 31;
    int b = w >> 6, tt = w & 63;
    const float* h = g_H2 + ((size_t)tt * B_ + b) * H_;
    float s = 0.f;
#pragma unroll
    for (int q = 0; q < H_ / 32; q++) s += h[lane + 32 * q] * Wfc[lane + 32 * q];
#pragma unroll
    for (int off = 16; off; off >>= 1) s += __shfl_down_sync(0xffffffffu, s, off);
    if (lane == 0) out[(size_t)b * L_ + tt] = s + bfc[0];
}

__global__ __launch_bounds__(256) void k_copy(float* __restrict__ out) {
    int i = blockIdx.x * 256 + threadIdx.x;
    const int n = B_ * H_;
    if (i < n) {
        out[B_ * L_ + i] = g_H1fin[i];
        out[B_ * L_ + n + i] = g_H2[(size_t)(L_ - 1) * n + i];
    }
}

// ---------------------------------------------------------------------------
extern "C" void kernel_launch(void* const* d_in, const int* in_sizes, int n_in,
                              void* d_out, int out_size) {
    const float* x    = (const float*)d_in[0];
    const float* h1i  = (const float*)d_in[1];
    const float* h2i  = (const float*)d_in[2];
    const float* Wih1 = (const float*)d_in[3];
    const float* Whh1 = (const float*)d_in[4];
    const float* bih1 = (const float*)d_in[5];
    const float* bhh1 = (const float*)d_in[6];
    const float* Wih2 = (const float*)d_in[7];
    const float* Whh2 = (const float*)d_in[8];
    const float* bih2 = (const float*)d_in[9];
    const float* bhh2 = (const float*)d_in[10];
    const float* Wfc  = (const float*)d_in[11];
    const float* bfc  = (const float*)d_in[12];
    float* out = (float*)d_out;

    cudaFuncSetAttribute(k_steps, cudaFuncAttributeMaxDynamicSharedMemorySize, SMTOT_);

    void* bar_addr = nullptr;
    cudaGetSymbolAddress(&bar_addr, g_bars);
    cudaMemsetAsync(bar_addr, 0, 512 * sizeof(unsigned));

    k_prep_w<<<(G3_ * H_ + 255) / 256, 256>>>(Wih1, Whh1, Wih2, Whh2);
    k_prep_h<<<(B_ * H_ + 255) / 256, 256>>>(h1i, h2i);
    k_prep_x<<<(L_ * B_ * H_ + 255) / 256, 256>>>(x);

    k_steps<<<128, 512, SMTOT_>>>(h1i, h2i, bih1, bhh1, bih2, bhh2);

    k_fc<<<4096, 256>>>(Wfc, bfc, out);
    k_copy<<<(B_ * H_ + 255) / 256, 256>>>(out);
}